// round 1
// baseline (speedup 1.0000x reference)
#include <cuda_runtime.h>
#include <cstdint>
#include <math.h>

// Problem constants (CausalMessagePassingLayer_90237262889057)
static constexpr int B_  = 4;
static constexpr int N_  = 4096;
static constexpr int M_  = 16384;
static constexpr int EG_ = 65536;
static constexpr int EA_ = 65536;
static constexpr int D_  = 512;
static constexpr int DK_ = 64;

// ---------------- scratch (single __device__ pool, reused across batches) ----
static constexpr size_t OFF_XW   = 0;
static constexpr size_t OFF_EDGE = OFF_XW   + (size_t)M_ * D_;
static constexpr size_t OFF_K    = OFF_EDGE + (size_t)M_ * D_;
static constexpr size_t OFF_Q    = OFF_K    + (size_t)M_ * DK_;
static constexpr size_t OFF_DINV = OFF_Q    + (size_t)N_ * DK_;
static constexpr size_t OFF_DEG  = OFF_DINV + M_;
static constexpr size_t OFF_MVAL = OFF_DEG  + M_;
static constexpr size_t OFF_DEN  = OFF_MVAL + N_;
static constexpr size_t OFF_DOTS = OFF_DEN  + N_;
static constexpr size_t OFF_W    = OFF_DOTS + EA_;
static constexpr size_t OFF_GATT = OFF_W    + EA_;
static constexpr size_t OFF_NEW1 = OFF_GATT + (size_t)N_ * D_;
static constexpr size_t OFF_MENC = OFF_NEW1 + (size_t)N_ * D_;
static constexpr size_t SCRATCH_FLOATS = OFF_MENC + N_;

__device__ float g_scratch[SCRATCH_FLOATS];

// ---------------- generic tiled SGEMM ---------------------------------------
// C[r][c] over Mrows x Ncols, K inner. A row-major lda=K (optionally row-gathered
// via gidx). B row-major [K, Ncols]. Epilogue:
//   v = acc (+ bias[c])
//   if resid: v = resid[r][c] + tanhf(gate[0]) * v
template <int BM, int BN, int BK, int TM, int TN>
__global__ void __launch_bounds__((BM / TM) * (BN / TN))
sgemm_k(int Mrows, int Ncols, int K,
        const float* __restrict__ A,
        const int*   __restrict__ gidx,
        const float* __restrict__ Bm,
        const float* __restrict__ bias,
        const float* __restrict__ resid,
        const float* __restrict__ gate,
        float* __restrict__ C)
{
    constexpr int THREADS = (BM / TM) * (BN / TN);
    __shared__ float As[BK][BM];
    __shared__ float Bs[BK][BN];

    const int tid = threadIdx.x;
    const int block_row = blockIdx.x * BM;
    const int block_col = blockIdx.y * BN;
    const int tx = tid % (BN / TN);
    const int ty = tid / (BN / TN);

    float acc[TM][TN];
#pragma unroll
    for (int i = 0; i < TM; i++)
#pragma unroll
        for (int j = 0; j < TN; j++) acc[i][j] = 0.f;

    for (int k0 = 0; k0 < K; k0 += BK) {
        // load A tile (BM x BK) as float4, transpose into As[k][m]
#pragma unroll
        for (int i = tid; i < BM * BK / 4; i += THREADS) {
            int r  = i / (BK / 4);
            int c4 = (i % (BK / 4)) * 4;
            int row = block_row + r;
            int ar = gidx ? __ldg(gidx + row) : row;
            float4 v = *reinterpret_cast<const float4*>(A + (size_t)ar * K + k0 + c4);
            As[c4 + 0][r] = v.x;
            As[c4 + 1][r] = v.y;
            As[c4 + 2][r] = v.z;
            As[c4 + 3][r] = v.w;
        }
        // load B tile (BK x BN) as float4
#pragma unroll
        for (int i = tid; i < BK * BN / 4; i += THREADS) {
            int r  = i / (BN / 4);
            int c4 = (i % (BN / 4)) * 4;
            float4 v = *reinterpret_cast<const float4*>(Bm + (size_t)(k0 + r) * Ncols + block_col + c4);
            *reinterpret_cast<float4*>(&Bs[r][c4]) = v;
        }
        __syncthreads();

#pragma unroll
        for (int kk = 0; kk < BK; kk++) {
            float ra[TM], rb[TN];
#pragma unroll
            for (int i = 0; i < TM; i++) ra[i] = As[kk][ty * TM + i];
#pragma unroll
            for (int j = 0; j < TN; j++) rb[j] = Bs[kk][tx * TN + j];
#pragma unroll
            for (int i = 0; i < TM; i++)
#pragma unroll
                for (int j = 0; j < TN; j++)
                    acc[i][j] = fmaf(ra[i], rb[j], acc[i][j]);
        }
        __syncthreads();
    }

    const float g = gate ? tanhf(gate[0]) : 0.f;
#pragma unroll
    for (int i = 0; i < TM; i++) {
        int r = block_row + ty * TM + i;
#pragma unroll
        for (int j = 0; j < TN; j++) {
            int c = block_col + tx * TN + j;
            float v = acc[i][j];
            if (bias)  v += __ldg(bias + c);
            if (resid) v = resid[(size_t)r * Ncols + c] + g * v;
            C[(size_t)r * Ncols + c] = v;
        }
    }
}

// ---------------- small kernels ----------------------------------------------
__global__ void init_batch_k(float* __restrict__ deg, unsigned* __restrict__ menc,
                             float* __restrict__ den, float* __restrict__ gatt)
{
    int i = blockIdx.x * blockDim.x + threadIdx.x;
    if (i < M_) deg[i] = 1.0f;                 // self-loop
    if (i < N_) { menc[i] = 0u; den[i] = 0.f; }
    if (i < N_ * D_) gatt[i] = 0.f;
}

__global__ void deg_add_k(const int* __restrict__ dst, float* __restrict__ deg)
{
    int e = blockIdx.x * blockDim.x + threadIdx.x;
    if (e < EG_) atomicAdd(&deg[dst[e]], 1.0f);
}

__global__ void dinv_k(const float* __restrict__ deg, float* __restrict__ dinv)
{
    int i = blockIdx.x * blockDim.x + threadIdx.x;
    if (i < M_) dinv[i] = rsqrtf(deg[i]);
}

// edge[m] = b_gnn + dinv[m]^2 * xw[m]   (self-loop term + bias)
__global__ void gcn_self_k(const float* __restrict__ xw, const float* __restrict__ dinv,
                           const float* __restrict__ bg, float* __restrict__ out)
{
    int idx = blockIdx.x * blockDim.x + threadIdx.x;
    if (idx >= M_ * (D_ / 4)) return;
    int m = idx >> 7;            // D_/4 == 128
    int j = (idx & 127) << 2;
    float dv = dinv[m];
    float c = dv * dv;
    float4 v = *reinterpret_cast<const float4*>(xw + (size_t)m * D_ + j);
    float4 b = *reinterpret_cast<const float4*>(bg + j);
    float4 o;
    o.x = b.x + c * v.x; o.y = b.y + c * v.y; o.z = b.z + c * v.z; o.w = b.w + c * v.w;
    *reinterpret_cast<float4*>(out + (size_t)m * D_ + j) = o;
}

// out[dst] += dinv[src]*dinv[dst] * xw[src]
__global__ void gcn_scatter_k(const float* __restrict__ xw, const float* __restrict__ dinv,
                              const int* __restrict__ src, const int* __restrict__ dst,
                              float* __restrict__ out)
{
    int idx = blockIdx.x * blockDim.x + threadIdx.x;
    if (idx >= EG_ * (D_ / 4)) return;
    int e = idx >> 7;
    int j = (idx & 127) << 2;
    int s = __ldg(src + e), d = __ldg(dst + e);
    float c = __ldg(dinv + s) * __ldg(dinv + d);
    float4 v = *reinterpret_cast<const float4*>(xw + (size_t)s * D_ + j);
    float* o = out + (size_t)d * D_ + j;
    atomicAdd(o + 0, c * v.x);
    atomicAdd(o + 1, c * v.y);
    atomicAdd(o + 2, c * v.z);
    atomicAdd(o + 3, c * v.w);
}

__device__ __forceinline__ unsigned f32_enc(float f) {
    unsigned u = __float_as_uint(f);
    return (u & 0x80000000u) ? ~u : (u | 0x80000000u);
}

// warp per attention edge: dot(q[dst], k[src]) / 8, segment-max via atomicMax
__global__ void att_dot_k(const float* __restrict__ q, const float* __restrict__ k,
                          const int* __restrict__ es, const int* __restrict__ ed,
                          float* __restrict__ dots, unsigned* __restrict__ menc)
{
    int e = (blockIdx.x * blockDim.x + threadIdx.x) >> 5;
    int lane = threadIdx.x & 31;
    if (e >= EA_) return;
    int s = __ldg(es + e), d = __ldg(ed + e);
    const float* qp = q + (size_t)d * DK_;
    const float* kp = k + (size_t)s * DK_;
    float v = qp[lane] * kp[lane] + qp[lane + 32] * kp[lane + 32];
#pragma unroll
    for (int off = 16; off; off >>= 1) v += __shfl_xor_sync(0xFFFFFFFFu, v, off);
    if (lane == 0) {
        v *= 0.125f;
        dots[e] = v;
        atomicMax(&menc[d], f32_enc(v));
    }
}

__global__ void att_m_k(const unsigned* __restrict__ menc, float* __restrict__ m)
{
    int i = blockIdx.x * blockDim.x + threadIdx.x;
    if (i >= N_) return;
    unsigned u = menc[i];
    float f = (u & 0x80000000u) ? __uint_as_float(u ^ 0x80000000u) : __uint_as_float(~u);
    m[i] = isfinite(f) ? f : 0.f;
}

__global__ void att_w_k(const float* __restrict__ dots, const float* __restrict__ m,
                        const int* __restrict__ ed, float* __restrict__ w,
                        float* __restrict__ den)
{
    int e = blockIdx.x * blockDim.x + threadIdx.x;
    if (e >= EA_) return;
    int d = ed[e];
    float wv = expf(dots[e] - m[d]);
    w[e] = wv;
    atomicAdd(&den[d], wv);
}

// gatt[dst] += (w[e]/den[dst]) * vals[src]
__global__ void att_scatter_k(const float* __restrict__ w, const float* __restrict__ den,
                              const float* __restrict__ vals,
                              const int* __restrict__ es, const int* __restrict__ ed,
                              float* __restrict__ gatt)
{
    int idx = blockIdx.x * blockDim.x + threadIdx.x;
    if (idx >= EA_ * (D_ / 4)) return;
    int e = idx >> 7;
    int j = (idx & 127) << 2;
    int s = __ldg(es + e), d = __ldg(ed + e);
    float dn = __ldg(den + d);
    float sc = __ldg(w + e) / (dn > 0.f ? dn : 1.f);
    float4 v = *reinterpret_cast<const float4*>(vals + (size_t)s * D_ + j);
    float* o = gatt + (size_t)d * D_ + j;
    atomicAdd(o + 0, sc * v.x);
    atomicAdd(o + 1, sc * v.y);
    atomicAdd(o + 2, sc * v.z);
    atomicAdd(o + 3, sc * v.w);
}

// new1 = tok + tanh(ga) * gatt
__global__ void new1_k(const float* __restrict__ tok, const float* __restrict__ gatt,
                       const float* __restrict__ ga, float* __restrict__ out)
{
    int idx = blockIdx.x * blockDim.x + threadIdx.x;
    if (idx >= N_ * (D_ / 4)) return;
    float g = tanhf(ga[0]);
    float4 t = reinterpret_cast<const float4*>(tok)[idx];
    float4 a = reinterpret_cast<const float4*>(gatt)[idx];
    float4 o;
    o.x = t.x + g * a.x; o.y = t.y + g * a.y; o.z = t.z + g * a.z; o.w = t.w + g * a.w;
    reinterpret_cast<float4*>(out)[idx] = o;
}

// ---------------- launch -------------------------------------------------------
extern "C" void kernel_launch(void* const* d_in, const int* in_sizes, int n_in,
                              void* d_out, int out_size)
{
    (void)in_sizes; (void)n_in; (void)out_size;

    const float* tok_all = (const float*)d_in[0];
    const int*   t2e_all = (const int*)d_in[1];
    const int*   ei_all  = (const int*)d_in[2];
    const int*   es_all  = (const int*)d_in[3];
    const int*   ed_all  = (const int*)d_in[4];
    const float* Wg = (const float*)d_in[5];
    const float* bg = (const float*)d_in[6];
    const float* Wk = (const float*)d_in[7];
    const float* bk = (const float*)d_in[8];
    const float* Wq = (const float*)d_in[9];
    const float* bq = (const float*)d_in[10];
    const float* Wl = (const float*)d_in[11];
    const float* bl = (const float*)d_in[12];
    const float* ga = (const float*)d_in[13];
    const float* gb = (const float*)d_in[14];
    float* out = (float*)d_out;

    float* base = nullptr;
    cudaGetSymbolAddress((void**)&base, g_scratch);

    float*    xw   = base + OFF_XW;
    float*    edge = base + OFF_EDGE;
    float*    kbuf = base + OFF_K;
    float*    qbuf = base + OFF_Q;
    float*    dinv = base + OFF_DINV;
    float*    deg  = base + OFF_DEG;
    float*    mval = base + OFF_MVAL;
    float*    den  = base + OFF_DEN;
    float*    dots = base + OFF_DOTS;
    float*    wbuf = base + OFF_W;
    float*    gatt = base + OFF_GATT;
    float*    new1 = base + OFF_NEW1;
    unsigned* menc = (unsigned*)(base + OFF_MENC);

    const int T = 256;

    for (int b = 0; b < B_; b++) {
        const float* tok = tok_all + (size_t)b * N_ * D_;
        const int*   t2e = t2e_all + (size_t)b * M_;
        const int*   esrc = ei_all + (size_t)b * 2 * EG_;
        const int*   edst = esrc + EG_;
        const int*   aes  = es_all + (size_t)b * EA_;
        const int*   aed  = ed_all + (size_t)b * EA_;
        float*       outb = out + (size_t)b * N_ * D_;

        // batch init (deg=1, menc=0, den=0, gatt=0)
        init_batch_k<<<(N_ * D_ + T - 1) / T, T>>>(deg, menc, den, gatt);

        // xw = tok[t2e] @ W_gnn   (gather fused into GEMM A-load)
        {
            dim3 grid(M_ / 128, D_ / 128);
            sgemm_k<128, 128, 8, 8, 8><<<grid, 256>>>(
                M_, D_, D_, tok, t2e, Wg, nullptr, nullptr, nullptr, xw);
        }

        // degrees / dinv
        deg_add_k<<<(EG_ + T - 1) / T, T>>>(edst, deg);
        dinv_k<<<(M_ + T - 1) / T, T>>>(deg, dinv);

        // edge = b_gnn + dinv^2 * xw  (self-loop), then scatter edges
        gcn_self_k<<<(M_ * (D_ / 4) + T - 1) / T, T>>>(xw, dinv, bg, edge);
        gcn_scatter_k<<<(EG_ * (D_ / 4) + T - 1) / T, T>>>(xw, dinv, esrc, edst, edge);

        // k = edge @ Wk + bk ; q = tok @ Wq + bq
        {
            dim3 gridk(M_ / 64, DK_ / 64);
            sgemm_k<64, 64, 16, 4, 4><<<gridk, 256>>>(
                M_, DK_, D_, edge, nullptr, Wk, bk, nullptr, nullptr, kbuf);
            dim3 gridq(N_ / 64, DK_ / 64);
            sgemm_k<64, 64, 16, 4, 4><<<gridq, 256>>>(
                N_, DK_, D_, tok, nullptr, Wq, bq, nullptr, nullptr, qbuf);
        }

        // attention: dots + segment max, softmax weights, scatter values
        att_dot_k<<<(EA_ * 32 + T - 1) / T, T>>>(qbuf, kbuf, aes, aed, dots, menc);
        att_m_k<<<(N_ + T - 1) / T, T>>>(menc, mval);
        att_w_k<<<(EA_ + T - 1) / T, T>>>(dots, mval, aed, wbuf, den);
        att_scatter_k<<<(EA_ * (D_ / 4) + T - 1) / T, T>>>(wbuf, den, edge, aes, aed, gatt);

        // new1 = tok + tanh(ga)*gatt
        new1_k<<<(N_ * (D_ / 4) + T - 1) / T, T>>>(tok, gatt, ga, new1);

        // out = new1 + tanh(gb) * (new1 @ Wl + bl)
        {
            dim3 grid(N_ / 128, D_ / 128);
            sgemm_k<128, 128, 8, 8, 8><<<grid, 256>>>(
                N_, D_, D_, new1, nullptr, Wl, bl, new1, gb, outb);
        }
    }
}

// round 2
// speedup vs baseline: 2.3827x; 2.3827x over previous
#include <cuda_runtime.h>
#include <cstdint>
#include <math.h>

// Problem constants (CausalMessagePassingLayer_90237262889057)
static constexpr int B_  = 4;
static constexpr int N_  = 4096;
static constexpr int M_  = 16384;
static constexpr int EG_ = 65536;
static constexpr int EA_ = 65536;
static constexpr int D_  = 512;
static constexpr int DK_ = 64;

static constexpr int BN_ALL = B_ * N_;   // 16384
static constexpr int BM_ALL = B_ * M_;   // 65536

// ---------------- scratch pool ------------------------------------------------
static constexpr size_t OFF_TW   = 0;                                  // [B*N, D]
static constexpr size_t OFF_EDGE = OFF_TW   + (size_t)BN_ALL * D_;     // [B*M, D]
static constexpr size_t OFF_K    = OFF_EDGE + (size_t)BM_ALL * D_;     // [B*M, DK]
static constexpr size_t OFF_Q    = OFF_K    + (size_t)BM_ALL * DK_;    // [B*N, DK]
static constexpr size_t OFF_NEW1 = OFF_Q    + (size_t)BN_ALL * DK_;    // [B*N, D]
static constexpr size_t OFF_GATT = OFF_NEW1 + (size_t)BN_ALL * D_;     // [B*N, D]
static constexpr size_t OFF_DEG  = OFF_GATT + (size_t)BN_ALL * D_;     // [B*M]
static constexpr size_t OFF_MENC = OFF_DEG  + BM_ALL;                  // [B*N]
static constexpr size_t OFF_DEN  = OFF_MENC + BN_ALL;                  // [B*N]
static constexpr size_t OFF_DOTS = OFF_DEN  + BN_ALL;                  // [B*EA]
static constexpr size_t OFF_W    = OFF_DOTS + (size_t)B_ * EA_;        // [B*EA]
static constexpr size_t SCRATCH_FLOATS = OFF_W + (size_t)B_ * EA_;

__device__ float g_scratch[SCRATCH_FLOATS];

// ---------------- helpers -------------------------------------------------------
__device__ __forceinline__ void red_add_v4(float* p, float x, float y, float z, float w)
{
    unsigned long long g = __cvta_generic_to_global((void*)p);
    asm volatile("red.global.add.v4.f32 [%0], {%1,%2,%3,%4};"
                 :: "l"(g), "f"(x), "f"(y), "f"(z), "f"(w) : "memory");
}

__device__ __forceinline__ unsigned f32_enc(float f) {
    unsigned u = __float_as_uint(f);
    return (u & 0x80000000u) ? ~u : (u | 0x80000000u);
}
__device__ __forceinline__ float f32_dec(unsigned u) {
    return (u & 0x80000000u) ? __uint_as_float(u ^ 0x80000000u) : __uint_as_float(~u);
}

// ---------------- generic tiled SGEMM -------------------------------------------
// C = A[Mrows,K] @ B[K,Ncols] (+ bias[c]); if resid: C = resid + tanh(gate)*C
template <int BM, int BN, int BK, int TM, int TN>
__global__ void __launch_bounds__((BM / TM) * (BN / TN))
sgemm_k(int Mrows, int Ncols, int K,
        const float* __restrict__ A,
        const float* __restrict__ Bm,
        const float* __restrict__ bias,
        const float* __restrict__ resid,
        const float* __restrict__ gate,
        float* __restrict__ C)
{
    constexpr int THREADS = (BM / TM) * (BN / TN);
    __shared__ float As[BK][BM];
    __shared__ float Bs[BK][BN];

    const int tid = threadIdx.x;
    const int block_row = blockIdx.x * BM;
    const int block_col = blockIdx.y * BN;
    const int tx = tid % (BN / TN);
    const int ty = tid / (BN / TN);

    float acc[TM][TN];
#pragma unroll
    for (int i = 0; i < TM; i++)
#pragma unroll
        for (int j = 0; j < TN; j++) acc[i][j] = 0.f;

    for (int k0 = 0; k0 < K; k0 += BK) {
#pragma unroll
        for (int i = tid; i < BM * BK / 4; i += THREADS) {
            int r  = i / (BK / 4);
            int c4 = (i % (BK / 4)) * 4;
            float4 v = *reinterpret_cast<const float4*>(A + (size_t)(block_row + r) * K + k0 + c4);
            As[c4 + 0][r] = v.x;
            As[c4 + 1][r] = v.y;
            As[c4 + 2][r] = v.z;
            As[c4 + 3][r] = v.w;
        }
#pragma unroll
        for (int i = tid; i < BK * BN / 4; i += THREADS) {
            int r  = i / (BN / 4);
            int c4 = (i % (BN / 4)) * 4;
            float4 v = *reinterpret_cast<const float4*>(Bm + (size_t)(k0 + r) * Ncols + block_col + c4);
            *reinterpret_cast<float4*>(&Bs[r][c4]) = v;
        }
        __syncthreads();

#pragma unroll
        for (int kk = 0; kk < BK; kk++) {
            float ra[TM], rb[TN];
#pragma unroll
            for (int i = 0; i < TM; i++) ra[i] = As[kk][ty * TM + i];
#pragma unroll
            for (int j = 0; j < TN; j++) rb[j] = Bs[kk][tx * TN + j];
#pragma unroll
            for (int i = 0; i < TM; i++)
#pragma unroll
                for (int j = 0; j < TN; j++)
                    acc[i][j] = fmaf(ra[i], rb[j], acc[i][j]);
        }
        __syncthreads();
    }

    const float g = gate ? tanhf(gate[0]) : 0.f;
#pragma unroll
    for (int i = 0; i < TM; i++) {
        int r = block_row + ty * TM + i;
#pragma unroll
        for (int j = 0; j < TN; j++) {
            int c = block_col + tx * TN + j;
            float v = acc[i][j];
            if (bias)  v += __ldg(bias + c);
            if (resid) v = resid[(size_t)r * Ncols + c] + g * v;
            C[(size_t)r * Ncols + c] = v;
        }
    }
}

// ---------------- batched elementwise / scatter kernels --------------------------
__global__ void init_k(float* __restrict__ deg, unsigned* __restrict__ menc,
                       float* __restrict__ den, float* __restrict__ gatt)
{
    int i = blockIdx.x * blockDim.x + threadIdx.x;
    if (i < (int)((size_t)BN_ALL * D_ / 4)) reinterpret_cast<float4*>(gatt)[i] = make_float4(0.f, 0.f, 0.f, 0.f);
    if (i < BM_ALL) deg[i] = 1.0f;           // self-loop
    if (i < BN_ALL) { menc[i] = 0u; den[i] = 0.f; }
}

__global__ void deg_add_k(const int* __restrict__ ei_all, float* __restrict__ deg)
{
    int i = blockIdx.x * blockDim.x + threadIdx.x;
    if (i >= B_ * EG_) return;
    int b = i >> 16;                 // EG_ = 65536
    int e = i & (EG_ - 1);
    int d = __ldg(ei_all + (size_t)b * 2 * EG_ + EG_ + e);
    atomicAdd(deg + b * M_ + d, 1.0f);
}

// edge[b,m] = b_gnn + (1/deg) * tw[b, t2e[b,m]]
__global__ void gcn_self_k(const float* __restrict__ tw, const float* __restrict__ deg,
                           const int* __restrict__ t2e_all, const float* __restrict__ bg,
                           float* __restrict__ edge)
{
    int idx = blockIdx.x * blockDim.x + threadIdx.x;
    if (idx >= BM_ALL * (D_ / 4)) return;
    int mg = idx >> 7;               // D_/4 = 128
    int j  = (idx & 127) << 2;
    int b  = mg >> 14;               // M_ = 16384
    int m  = mg & (M_ - 1);
    float dv = rsqrtf(__ldg(deg + mg));
    float c = dv * dv;
    int trow = __ldg(t2e_all + (size_t)b * M_ + m);
    float4 v = *reinterpret_cast<const float4*>(tw + ((size_t)b * N_ + trow) * D_ + j);
    float4 bb = *reinterpret_cast<const float4*>(bg + j);
    float4 o;
    o.x = bb.x + c * v.x; o.y = bb.y + c * v.y; o.z = bb.z + c * v.z; o.w = bb.w + c * v.w;
    *reinterpret_cast<float4*>(edge + (size_t)mg * D_ + j) = o;
}

// edge[b,d] += dinv[s]*dinv[d] * tw[b, t2e[b,s]]
__global__ void gcn_scatter_k(const float* __restrict__ tw, const float* __restrict__ deg,
                              const int* __restrict__ t2e_all, const int* __restrict__ ei_all,
                              float* __restrict__ edge)
{
    int idx = blockIdx.x * blockDim.x + threadIdx.x;
    if (idx >= B_ * EG_ * (D_ / 4)) return;
    int eg = idx >> 7;
    int j  = (idx & 127) << 2;
    int b  = eg >> 16;               // EG_ = 65536
    int e  = eg & (EG_ - 1);
    const int* ei = ei_all + (size_t)b * 2 * EG_;
    int s = __ldg(ei + e), d = __ldg(ei + EG_ + e);
    float c = rsqrtf(__ldg(deg + b * M_ + s)) * rsqrtf(__ldg(deg + b * M_ + d));
    int trow = __ldg(t2e_all + (size_t)b * M_ + s);
    float4 v = *reinterpret_cast<const float4*>(tw + ((size_t)b * N_ + trow) * D_ + j);
    red_add_v4(edge + ((size_t)b * M_ + d) * D_ + j, c * v.x, c * v.y, c * v.z, c * v.w);
}

// warp per attention edge: dot(q[b,dst], k[b,src]) / 8; segment max via atomicMax
__global__ void att_dot_k(const float* __restrict__ q, const float* __restrict__ k,
                          const int* __restrict__ es_all, const int* __restrict__ ed_all,
                          float* __restrict__ dots, unsigned* __restrict__ menc)
{
    int eg = (blockIdx.x * blockDim.x + threadIdx.x) >> 5;
    int lane = threadIdx.x & 31;
    if (eg >= B_ * EA_) return;
    int b = eg >> 16;                // EA_ = 65536
    int e = eg & (EA_ - 1);
    int s = __ldg(es_all + (size_t)b * EA_ + e);
    int d = __ldg(ed_all + (size_t)b * EA_ + e);
    const float* qp = q + ((size_t)b * N_ + d) * DK_;
    const float* kp = k + ((size_t)b * M_ + s) * DK_;
    float v = qp[lane] * kp[lane] + qp[lane + 32] * kp[lane + 32];
#pragma unroll
    for (int off = 16; off; off >>= 1) v += __shfl_xor_sync(0xFFFFFFFFu, v, off);
    if (lane == 0) {
        v *= 0.125f;
        dots[eg] = v;
        atomicMax(&menc[b * N_ + d], f32_enc(v));
    }
}

__global__ void att_w_k(const float* __restrict__ dots, const unsigned* __restrict__ menc,
                        const int* __restrict__ ed_all, float* __restrict__ w,
                        float* __restrict__ den)
{
    int eg = blockIdx.x * blockDim.x + threadIdx.x;
    if (eg >= B_ * EA_) return;
    int b = eg >> 16;
    int e = eg & (EA_ - 1);
    int d = __ldg(ed_all + (size_t)b * EA_ + e);
    float m = f32_dec(menc[b * N_ + d]);
    if (!isfinite(m)) m = 0.f;
    float wv = expf(dots[eg] - m);
    w[eg] = wv;
    atomicAdd(&den[b * N_ + d], wv);
}

// gatt[b,dst] += (w/den[dst]) * edge[b,src]
__global__ void att_scatter_k(const float* __restrict__ w, const float* __restrict__ den,
                              const float* __restrict__ edge,
                              const int* __restrict__ es_all, const int* __restrict__ ed_all,
                              float* __restrict__ gatt)
{
    int idx = blockIdx.x * blockDim.x + threadIdx.x;
    if (idx >= B_ * EA_ * (D_ / 4)) return;
    int eg = idx >> 7;
    int j  = (idx & 127) << 2;
    int b  = eg >> 16;
    int e  = eg & (EA_ - 1);
    int s = __ldg(es_all + (size_t)b * EA_ + e);
    int d = __ldg(ed_all + (size_t)b * EA_ + e);
    float dn = __ldg(den + b * N_ + d);
    float sc = __ldg(w + eg) / (dn > 0.f ? dn : 1.f);
    float4 v = *reinterpret_cast<const float4*>(edge + ((size_t)b * M_ + s) * D_ + j);
    red_add_v4(gatt + ((size_t)b * N_ + d) * D_ + j, sc * v.x, sc * v.y, sc * v.z, sc * v.w);
}

// new1 = tok + tanh(ga) * gatt
__global__ void new1_k(const float* __restrict__ tok, const float* __restrict__ gatt,
                       const float* __restrict__ ga, float* __restrict__ out)
{
    int idx = blockIdx.x * blockDim.x + threadIdx.x;
    if (idx >= (int)((size_t)BN_ALL * D_ / 4)) return;
    float g = tanhf(ga[0]);
    float4 t = reinterpret_cast<const float4*>(tok)[idx];
    float4 a = reinterpret_cast<const float4*>(gatt)[idx];
    float4 o;
    o.x = t.x + g * a.x; o.y = t.y + g * a.y; o.z = t.z + g * a.z; o.w = t.w + g * a.w;
    reinterpret_cast<float4*>(out)[idx] = o;
}

// ---------------- launch ----------------------------------------------------------
extern "C" void kernel_launch(void* const* d_in, const int* in_sizes, int n_in,
                              void* d_out, int out_size)
{
    (void)in_sizes; (void)n_in; (void)out_size;

    const float* tok = (const float*)d_in[0];   // [B*N, D]
    const int*   t2e = (const int*)d_in[1];     // [B, M]
    const int*   ei  = (const int*)d_in[2];     // [B, 2, EG]
    const int*   aes = (const int*)d_in[3];     // [B, EA]
    const int*   aed = (const int*)d_in[4];     // [B, EA]
    const float* Wg = (const float*)d_in[5];
    const float* bg = (const float*)d_in[6];
    const float* Wk = (const float*)d_in[7];
    const float* bk = (const float*)d_in[8];
    const float* Wq = (const float*)d_in[9];
    const float* bq = (const float*)d_in[10];
    const float* Wl = (const float*)d_in[11];
    const float* bl = (const float*)d_in[12];
    const float* ga = (const float*)d_in[13];
    const float* gb = (const float*)d_in[14];
    float* out = (float*)d_out;

    float* base = nullptr;
    cudaGetSymbolAddress((void**)&base, g_scratch);

    float*    tw   = base + OFF_TW;
    float*    edge = base + OFF_EDGE;
    float*    kbuf = base + OFF_K;
    float*    qbuf = base + OFF_Q;
    float*    new1 = base + OFF_NEW1;
    float*    gatt = base + OFF_GATT;
    float*    deg  = base + OFF_DEG;
    unsigned* menc = (unsigned*)(base + OFF_MENC);
    float*    den  = base + OFF_DEN;
    float*    dots = base + OFF_DOTS;
    float*    wbuf = base + OFF_W;

    const int T = 256;

    // init: gatt=0, deg=1, menc=0, den=0
    init_k<<<(int)(((size_t)BN_ALL * D_ / 4 + T - 1) / T), T>>>(deg, menc, den, gatt);

    // tw = tok @ Wg  (gather moved AFTER the GEMM: (t[t2e])@W == (t@W)[t2e])
    {
        dim3 grid(BN_ALL / 128, D_ / 128);
        sgemm_k<128, 128, 8, 8, 8><<<grid, 256>>>(BN_ALL, D_, D_, tok, Wg,
                                                  nullptr, nullptr, nullptr, tw);
    }
    // q = tok @ Wq + bq
    {
        dim3 grid(BN_ALL / 128, DK_ / 64);
        sgemm_k<128, 64, 16, 8, 4><<<grid, 256>>>(BN_ALL, DK_, D_, tok, Wq,
                                                  bq, nullptr, nullptr, qbuf);
    }

    // degrees, GCN self-loop term + bias, GCN edge scatter
    deg_add_k<<<(B_ * EG_ + T - 1) / T, T>>>(ei, deg);
    gcn_self_k<<<(BM_ALL * (D_ / 4) + T - 1) / T, T>>>(tw, deg, t2e, bg, edge);
    gcn_scatter_k<<<(int)(((size_t)B_ * EG_ * (D_ / 4) + T - 1) / T), T>>>(tw, deg, t2e, ei, edge);

    // k = edge @ Wk + bk
    {
        dim3 grid(BM_ALL / 128, DK_ / 64);
        sgemm_k<128, 64, 16, 8, 4><<<grid, 256>>>(BM_ALL, DK_, D_, edge, Wk,
                                                  bk, nullptr, nullptr, kbuf);
    }

    // attention
    att_dot_k<<<(int)(((size_t)B_ * EA_ * 32 + T - 1) / T), T>>>(qbuf, kbuf, aes, aed, dots, menc);
    att_w_k<<<(B_ * EA_ + T - 1) / T, T>>>(dots, menc, aed, wbuf, den);
    att_scatter_k<<<(int)(((size_t)B_ * EA_ * (D_ / 4) + T - 1) / T), T>>>(wbuf, den, edge, aes, aed, gatt);

    // new1 = tok + tanh(ga)*gatt
    new1_k<<<(int)(((size_t)BN_ALL * D_ / 4 + T - 1) / T), T>>>(tok, gatt, ga, new1);

    // out = new1 + tanh(gb) * (new1 @ Wl + bl)
    {
        dim3 grid(BN_ALL / 128, D_ / 128);
        sgemm_k<128, 128, 8, 8, 8><<<grid, 256>>>(BN_ALL, D_, D_, new1, Wl,
                                                  bl, new1, gb, out);
    }
}

// round 3
// speedup vs baseline: 2.3847x; 1.0008x over previous
#include <cuda_runtime.h>
#include <cstdint>
#include <math.h>

// Problem constants (CausalMessagePassingLayer_90237262889057)
static constexpr int B_  = 4;
static constexpr int N_  = 4096;
static constexpr int M_  = 16384;
static constexpr int EG_ = 65536;
static constexpr int EA_ = 65536;
static constexpr int D_  = 512;
static constexpr int DK_ = 64;

static constexpr int BN_ALL = B_ * N_;   // 16384
static constexpr int BM_ALL = B_ * M_;   // 65536

// ---------------- scratch pool ------------------------------------------------
static constexpr size_t OFF_TW   = 0;                                  // [B*N, D]
static constexpr size_t OFF_EDGE = OFF_TW   + (size_t)BN_ALL * D_;     // [B*M, D]
static constexpr size_t OFF_K    = OFF_EDGE + (size_t)BM_ALL * D_;     // [B*M, DK]
static constexpr size_t OFF_Q    = OFF_K    + (size_t)BM_ALL * DK_;    // [B*N, DK]
static constexpr size_t OFF_NEW1 = OFF_Q    + (size_t)BN_ALL * DK_;    // [B*N, D]
static constexpr size_t OFF_GATT = OFF_NEW1 + (size_t)BN_ALL * D_;     // [B*N, D]
static constexpr size_t OFF_DEG  = OFF_GATT + (size_t)BN_ALL * D_;     // [B*M]
static constexpr size_t OFF_MENC = OFF_DEG  + BM_ALL;                  // [B*N]
static constexpr size_t OFF_DEN  = OFF_MENC + BN_ALL;                  // [B*N]
static constexpr size_t OFF_DOTS = OFF_DEN  + BN_ALL;                  // [B*EA]
static constexpr size_t OFF_W    = OFF_DOTS + (size_t)B_ * EA_;        // [B*EA]
static constexpr size_t SCRATCH_FLOATS = OFF_W + (size_t)B_ * EA_;

__device__ float g_scratch[SCRATCH_FLOATS];

// ---------------- helpers -------------------------------------------------------
__device__ __forceinline__ void red_add_v4(float* p, float x, float y, float z, float w)
{
    unsigned long long g = __cvta_generic_to_global((void*)p);
    asm volatile("red.global.add.v4.f32 [%0], {%1,%2,%3,%4};"
                 :: "l"(g), "f"(x), "f"(y), "f"(z), "f"(w) : "memory");
}

__device__ __forceinline__ unsigned f32_enc(float f) {
    unsigned u = __float_as_uint(f);
    return (u & 0x80000000u) ? ~u : (u | 0x80000000u);
}
__device__ __forceinline__ float f32_dec(unsigned u) {
    return (u & 0x80000000u) ? __uint_as_float(u ^ 0x80000000u) : __uint_as_float(~u);
}

__device__ __forceinline__ unsigned long long pack2(float x, float y) {
    unsigned long long r;
    asm("mov.b64 %0, {%1, %2};" : "=l"(r) : "f"(x), "f"(y));
    return r;
}
__device__ __forceinline__ void unpack2(unsigned long long v, float& x, float& y) {
    asm("mov.b64 {%0, %1}, %2;" : "=f"(x), "=f"(y) : "l"(v));
}
// packed dual-fp32 FMA: d = a*b + d  (FFMA2, exact fp32 semantics, 2x rate)
__device__ __forceinline__ void ffma2(unsigned long long& d, unsigned long long a,
                                      unsigned long long b) {
    asm("fma.rn.f32x2 %0, %1, %2, %0;" : "+l"(d) : "l"(a), "l"(b));
}

// ---------------- FFMA2 double-buffered SGEMM -----------------------------------
// C = A[Mrows,K] @ B[K,Ncols] (+ bias[c]); if resid: C = resid + tanh(gate)*C
template <int BM, int BN, int BK, int TM, int TN>
__global__ void __launch_bounds__((BM / TM) * (BN / TN))
sgemm_k(int Mrows, int Ncols, int K,
        const float* __restrict__ A,
        const float* __restrict__ Bm,
        const float* __restrict__ bias,
        const float* __restrict__ resid,
        const float* __restrict__ gate,
        float* __restrict__ C)
{
    constexpr int THREADS = (BM / TM) * (BN / TN);
    constexpr int PAD = 4;
    constexpr int NA = (BM * BK) / (4 * THREADS);   // float4 A loads per thread
    constexpr int NB = (BK * BN) / (4 * THREADS);   // float4 B loads per thread
    static_assert(NA >= 1 && NB >= 1, "tile/thread mismatch");

    __shared__ __align__(16) float As[2][BK][BM + PAD];
    __shared__ __align__(16) float Bs[2][BK][BN + PAD];

    const int tid = threadIdx.x;
    const int block_row = blockIdx.x * BM;
    const int block_col = blockIdx.y * BN;
    const int tx = tid % (BN / TN);
    const int ty = tid / (BN / TN);

    unsigned long long acc[TM][TN / 2];
#pragma unroll
    for (int i = 0; i < TM; i++)
#pragma unroll
        for (int j = 0; j < TN / 2; j++) acc[i][j] = 0ull;

    float4 ar[NA], br[NB];

    // prologue load (k0 = 0)
#pragma unroll
    for (int u = 0; u < NA; u++) {
        int i  = tid + u * THREADS;
        int r  = i / (BK / 4);
        int c4 = (i % (BK / 4)) * 4;
        ar[u] = *reinterpret_cast<const float4*>(A + (size_t)(block_row + r) * K + c4);
    }
#pragma unroll
    for (int u = 0; u < NB; u++) {
        int i  = tid + u * THREADS;
        int r  = i / (BN / 4);
        int c4 = (i % (BN / 4)) * 4;
        br[u] = *reinterpret_cast<const float4*>(Bm + (size_t)r * Ncols + block_col + c4);
    }

    int buf = 0;
    for (int k0 = 0; k0 < K; k0 += BK) {
        // store staged regs into smem[buf]
#pragma unroll
        for (int u = 0; u < NA; u++) {
            int i  = tid + u * THREADS;
            int r  = i / (BK / 4);
            int c4 = (i % (BK / 4)) * 4;
            As[buf][c4 + 0][r] = ar[u].x;
            As[buf][c4 + 1][r] = ar[u].y;
            As[buf][c4 + 2][r] = ar[u].z;
            As[buf][c4 + 3][r] = ar[u].w;
        }
#pragma unroll
        for (int u = 0; u < NB; u++) {
            int i  = tid + u * THREADS;
            int r  = i / (BN / 4);
            int c4 = (i % (BN / 4)) * 4;
            *reinterpret_cast<float4*>(&Bs[buf][r][c4]) = br[u];
        }
        __syncthreads();

        // stage next tile
        if (k0 + BK < K) {
#pragma unroll
            for (int u = 0; u < NA; u++) {
                int i  = tid + u * THREADS;
                int r  = i / (BK / 4);
                int c4 = (i % (BK / 4)) * 4;
                ar[u] = *reinterpret_cast<const float4*>(A + (size_t)(block_row + r) * K + k0 + BK + c4);
            }
#pragma unroll
            for (int u = 0; u < NB; u++) {
                int i  = tid + u * THREADS;
                int r  = i / (BN / 4);
                int c4 = (i % (BN / 4)) * 4;
                br[u] = *reinterpret_cast<const float4*>(Bm + (size_t)(k0 + BK + r) * Ncols + block_col + c4);
            }
        }

        // compute on smem[buf]
#pragma unroll
        for (int kk = 0; kk < BK; kk++) {
            const float* arow = &As[buf][kk][ty * TM];
            float4 a0 = *reinterpret_cast<const float4*>(arow);
            float4 a1 = *reinterpret_cast<const float4*>(arow + 4);
            ulonglong2 b01 = *reinterpret_cast<const ulonglong2*>(&Bs[buf][kk][tx * TN]);
            ulonglong2 b23 = *reinterpret_cast<const ulonglong2*>(&Bs[buf][kk][tx * TN + 4]);
            unsigned long long bp[4] = { b01.x, b01.y, b23.x, b23.y };
            unsigned long long ad[TM];
            ad[0] = pack2(a0.x, a0.x); ad[1] = pack2(a0.y, a0.y);
            ad[2] = pack2(a0.z, a0.z); ad[3] = pack2(a0.w, a0.w);
            ad[4] = pack2(a1.x, a1.x); ad[5] = pack2(a1.y, a1.y);
            ad[6] = pack2(a1.z, a1.z); ad[7] = pack2(a1.w, a1.w);
#pragma unroll
            for (int i = 0; i < TM; i++)
#pragma unroll
                for (int j = 0; j < TN / 2; j++)
                    ffma2(acc[i][j], ad[i], bp[j]);
        }
        buf ^= 1;
        __syncthreads();
    }

    const float g = gate ? tanhf(gate[0]) : 0.f;
#pragma unroll
    for (int i = 0; i < TM; i++) {
        int r = block_row + ty * TM + i;
#pragma unroll
        for (int j = 0; j < TN / 2; j++) {
            int c = block_col + tx * TN + 2 * j;
            float lo, hi;
            unpack2(acc[i][j], lo, hi);
            if (bias) { lo += __ldg(bias + c); hi += __ldg(bias + c + 1); }
            if (resid) {
                float2 rv = *reinterpret_cast<const float2*>(resid + (size_t)r * Ncols + c);
                lo = rv.x + g * lo;
                hi = rv.y + g * hi;
            }
            float2 ov; ov.x = lo; ov.y = hi;
            *reinterpret_cast<float2*>(C + (size_t)r * Ncols + c) = ov;
        }
    }
}

// ---------------- batched elementwise / scatter kernels --------------------------
__global__ void init_k(float* __restrict__ deg, unsigned* __restrict__ menc,
                       float* __restrict__ den, float* __restrict__ gatt)
{
    int i = blockIdx.x * blockDim.x + threadIdx.x;
    if (i < (int)((size_t)BN_ALL * D_ / 4)) reinterpret_cast<float4*>(gatt)[i] = make_float4(0.f, 0.f, 0.f, 0.f);
    if (i < BM_ALL) deg[i] = 1.0f;           // self-loop
    if (i < BN_ALL) { menc[i] = 0u; den[i] = 0.f; }
}

__global__ void deg_add_k(const int* __restrict__ ei_all, float* __restrict__ deg)
{
    int i = blockIdx.x * blockDim.x + threadIdx.x;
    if (i >= B_ * EG_) return;
    int b = i >> 16;                 // EG_ = 65536
    int e = i & (EG_ - 1);
    int d = __ldg(ei_all + (size_t)b * 2 * EG_ + EG_ + e);
    atomicAdd(deg + b * M_ + d, 1.0f);
}

// edge[b,m] = b_gnn + (1/deg) * tw[b, t2e[b,m]]
__global__ void gcn_self_k(const float* __restrict__ tw, const float* __restrict__ deg,
                           const int* __restrict__ t2e_all, const float* __restrict__ bg,
                           float* __restrict__ edge)
{
    int idx = blockIdx.x * blockDim.x + threadIdx.x;
    if (idx >= BM_ALL * (D_ / 4)) return;
    int mg = idx >> 7;               // D_/4 = 128
    int j  = (idx & 127) << 2;
    int b  = mg >> 14;               // M_ = 16384
    int m  = mg & (M_ - 1);
    float c = 1.0f / __ldg(deg + mg);
    int trow = __ldg(t2e_all + (size_t)b * M_ + m);
    float4 v = *reinterpret_cast<const float4*>(tw + ((size_t)b * N_ + trow) * D_ + j);
    float4 bb = *reinterpret_cast<const float4*>(bg + j);
    float4 o;
    o.x = bb.x + c * v.x; o.y = bb.y + c * v.y; o.z = bb.z + c * v.z; o.w = bb.w + c * v.w;
    *reinterpret_cast<float4*>(edge + (size_t)mg * D_ + j) = o;
}

// edge[b,d] += dinv[s]*dinv[d] * tw[b, t2e[b,s]]
__global__ void gcn_scatter_k(const float* __restrict__ tw, const float* __restrict__ deg,
                              const int* __restrict__ t2e_all, const int* __restrict__ ei_all,
                              float* __restrict__ edge)
{
    int idx = blockIdx.x * blockDim.x + threadIdx.x;
    if (idx >= B_ * EG_ * (D_ / 4)) return;
    int eg = idx >> 7;
    int j  = (idx & 127) << 2;
    int b  = eg >> 16;               // EG_ = 65536
    int e  = eg & (EG_ - 1);
    const int* ei = ei_all + (size_t)b * 2 * EG_;
    int s = __ldg(ei + e), d = __ldg(ei + EG_ + e);
    float c = rsqrtf(__ldg(deg + b * M_ + s)) * rsqrtf(__ldg(deg + b * M_ + d));
    int trow = __ldg(t2e_all + (size_t)b * M_ + s);
    float4 v = *reinterpret_cast<const float4*>(tw + ((size_t)b * N_ + trow) * D_ + j);
    red_add_v4(edge + ((size_t)b * M_ + d) * D_ + j, c * v.x, c * v.y, c * v.z, c * v.w);
}

// warp per attention edge: dot(q[b,dst], k[b,src]) / 8; segment max via atomicMax
__global__ void att_dot_k(const float* __restrict__ q, const float* __restrict__ k,
                          const int* __restrict__ es_all, const int* __restrict__ ed_all,
                          float* __restrict__ dots, unsigned* __restrict__ menc)
{
    int eg = (blockIdx.x * blockDim.x + threadIdx.x) >> 5;
    int lane = threadIdx.x & 31;
    if (eg >= B_ * EA_) return;
    int b = eg >> 16;                // EA_ = 65536
    int e = eg & (EA_ - 1);
    int s = __ldg(es_all + (size_t)b * EA_ + e);
    int d = __ldg(ed_all + (size_t)b * EA_ + e);
    const float* qp = q + ((size_t)b * N_ + d) * DK_;
    const float* kp = k + ((size_t)b * M_ + s) * DK_;
    float v = qp[lane] * kp[lane] + qp[lane + 32] * kp[lane + 32];
#pragma unroll
    for (int off = 16; off; off >>= 1) v += __shfl_xor_sync(0xFFFFFFFFu, v, off);
    if (lane == 0) {
        v *= 0.125f;
        dots[eg] = v;
        atomicMax(&menc[b * N_ + d], f32_enc(v));
    }
}

__global__ void att_w_k(const float* __restrict__ dots, const unsigned* __restrict__ menc,
                        const int* __restrict__ ed_all, float* __restrict__ w,
                        float* __restrict__ den)
{
    int eg = blockIdx.x * blockDim.x + threadIdx.x;
    if (eg >= B_ * EA_) return;
    int b = eg >> 16;
    int e = eg & (EA_ - 1);
    int d = __ldg(ed_all + (size_t)b * EA_ + e);
    float m = f32_dec(menc[b * N_ + d]);
    if (!isfinite(m)) m = 0.f;
    float wv = __expf(dots[eg] - m);
    w[eg] = wv;
    atomicAdd(&den[b * N_ + d], wv);
}

// gatt[b,dst] += (w/den[dst]) * edge[b,src]
__global__ void att_scatter_k(const float* __restrict__ w, const float* __restrict__ den,
                              const float* __restrict__ edge,
                              const int* __restrict__ es_all, const int* __restrict__ ed_all,
                              float* __restrict__ gatt)
{
    int idx = blockIdx.x * blockDim.x + threadIdx.x;
    if (idx >= B_ * EA_ * (D_ / 4)) return;
    int eg = idx >> 7;
    int j  = (idx & 127) << 2;
    int b  = eg >> 16;
    int e  = eg & (EA_ - 1);
    int s = __ldg(es_all + (size_t)b * EA_ + e);
    int d = __ldg(ed_all + (size_t)b * EA_ + e);
    float dn = __ldg(den + b * N_ + d);
    float sc = __ldg(w + eg) / (dn > 0.f ? dn : 1.f);
    float4 v = *reinterpret_cast<const float4*>(edge + ((size_t)b * M_ + s) * D_ + j);
    red_add_v4(gatt + ((size_t)b * N_ + d) * D_ + j, sc * v.x, sc * v.y, sc * v.z, sc * v.w);
}

// new1 = tok + tanh(ga) * gatt
__global__ void new1_k(const float* __restrict__ tok, const float* __restrict__ gatt,
                       const float* __restrict__ ga, float* __restrict__ out)
{
    int idx = blockIdx.x * blockDim.x + threadIdx.x;
    if (idx >= (int)((size_t)BN_ALL * D_ / 4)) return;
    float g = tanhf(ga[0]);
    float4 t = reinterpret_cast<const float4*>(tok)[idx];
    float4 a = reinterpret_cast<const float4*>(gatt)[idx];
    float4 o;
    o.x = t.x + g * a.x; o.y = t.y + g * a.y; o.z = t.z + g * a.z; o.w = t.w + g * a.w;
    reinterpret_cast<float4*>(out)[idx] = o;
}

// ---------------- launch ----------------------------------------------------------
extern "C" void kernel_launch(void* const* d_in, const int* in_sizes, int n_in,
                              void* d_out, int out_size)
{
    (void)in_sizes; (void)n_in; (void)out_size;

    const float* tok = (const float*)d_in[0];   // [B*N, D]
    const int*   t2e = (const int*)d_in[1];     // [B, M]
    const int*   ei  = (const int*)d_in[2];     // [B, 2, EG]
    const int*   aes = (const int*)d_in[3];     // [B, EA]
    const int*   aed = (const int*)d_in[4];     // [B, EA]
    const float* Wg = (const float*)d_in[5];
    const float* bg = (const float*)d_in[6];
    const float* Wk = (const float*)d_in[7];
    const float* bk = (const float*)d_in[8];
    const float* Wq = (const float*)d_in[9];
    const float* bq = (const float*)d_in[10];
    const float* Wl = (const float*)d_in[11];
    const float* bl = (const float*)d_in[12];
    const float* ga = (const float*)d_in[13];
    const float* gb = (const float*)d_in[14];
    float* out = (float*)d_out;

    float* base = nullptr;
    cudaGetSymbolAddress((void**)&base, g_scratch);

    float*    tw   = base + OFF_TW;
    float*    edge = base + OFF_EDGE;
    float*    kbuf = base + OFF_K;
    float*    qbuf = base + OFF_Q;
    float*    new1 = base + OFF_NEW1;
    float*    gatt = base + OFF_GATT;
    float*    deg  = base + OFF_DEG;
    unsigned* menc = (unsigned*)(base + OFF_MENC);
    float*    den  = base + OFF_DEN;
    float*    dots = base + OFF_DOTS;
    float*    wbuf = base + OFF_W;

    const int T = 256;

    // init: gatt=0, deg=1, menc=0, den=0
    init_k<<<(int)(((size_t)BN_ALL * D_ / 4 + T - 1) / T), T>>>(deg, menc, den, gatt);

    // tw = tok @ Wg   ((t[t2e])@W == (t@W)[t2e])
    {
        dim3 grid(BN_ALL / 128, D_ / 128);
        sgemm_k<128, 128, 16, 8, 8><<<grid, 256>>>(BN_ALL, D_, D_, tok, Wg,
                                                   nullptr, nullptr, nullptr, tw);
    }
    // q = tok @ Wq + bq
    {
        dim3 grid(BN_ALL / 128, DK_ / 64);
        sgemm_k<128, 64, 16, 8, 8><<<grid, 128>>>(BN_ALL, DK_, D_, tok, Wq,
                                                  bq, nullptr, nullptr, qbuf);
    }

    // degrees, GCN self-loop term + bias, GCN edge scatter
    deg_add_k<<<(B_ * EG_ + T - 1) / T, T>>>(ei, deg);
    gcn_self_k<<<(BM_ALL * (D_ / 4) + T - 1) / T, T>>>(tw, deg, t2e, bg, edge);
    gcn_scatter_k<<<(int)(((size_t)B_ * EG_ * (D_ / 4) + T - 1) / T), T>>>(tw, deg, t2e, ei, edge);

    // k = edge @ Wk + bk
    {
        dim3 grid(BM_ALL / 128, DK_ / 64);
        sgemm_k<128, 64, 16, 8, 8><<<grid, 128>>>(BM_ALL, DK_, D_, edge, Wk,
                                                  bk, nullptr, nullptr, kbuf);
    }

    // attention
    att_dot_k<<<(int)(((size_t)B_ * EA_ * 32 + T - 1) / T), T>>>(qbuf, kbuf, aes, aed, dots, menc);
    att_w_k<<<(B_ * EA_ + T - 1) / T, T>>>(dots, menc, aed, wbuf, den);
    att_scatter_k<<<(int)(((size_t)B_ * EA_ * (D_ / 4) + T - 1) / T), T>>>(wbuf, den, edge, aes, aed, gatt);

    // new1 = tok + tanh(ga)*gatt
    new1_k<<<(int)(((size_t)BN_ALL * D_ / 4 + T - 1) / T), T>>>(tok, gatt, ga, new1);

    // out = new1 + tanh(gb) * (new1 @ Wl + bl)
    {
        dim3 grid(BN_ALL / 128, D_ / 128);
        sgemm_k<128, 128, 16, 8, 8><<<grid, 256>>>(BN_ALL, D_, D_, new1, Wl,
                                                   bl, new1, gb, out);
    }
}

// round 8
// speedup vs baseline: 2.4654x; 1.0338x over previous
#include <cuda_runtime.h>
#include <cuda_bf16.h>
#include <cstdint>
#include <math.h>

// Problem constants (CausalMessagePassingLayer_90237262889057)
static constexpr int B_  = 4;
static constexpr int N_  = 4096;
static constexpr int M_  = 16384;
static constexpr int EG_ = 65536;
static constexpr int EA_ = 65536;
static constexpr int D_  = 512;
static constexpr int DK_ = 64;

static constexpr int BN_ALL = B_ * N_;   // 16384
static constexpr int BM_ALL = B_ * M_;   // 65536

// ---------------- scratch pool ------------------------------------------------
static constexpr size_t OFF_TW   = 0;                                  // [B*N, D] f32
static constexpr size_t OFF_EDGE = OFF_TW   + (size_t)BN_ALL * D_;     // [B*M, D] f32
static constexpr size_t OFF_K    = OFF_EDGE + (size_t)BM_ALL * D_;     // [B*M, DK]
static constexpr size_t OFF_Q    = OFF_K    + (size_t)BM_ALL * DK_;    // [B*N, DK]
static constexpr size_t OFF_NEW1 = OFF_Q    + (size_t)BN_ALL * DK_;    // [B*N, D]
static constexpr size_t OFF_GATT = OFF_NEW1 + (size_t)BN_ALL * D_;     // [B*N, D]
static constexpr size_t OFF_DEG  = OFF_GATT + (size_t)BN_ALL * D_;     // [B*M]
static constexpr size_t OFF_MENC = OFF_DEG  + BM_ALL;                  // [B*N]
static constexpr size_t OFF_DEN  = OFF_MENC + BN_ALL;                  // [B*N]
static constexpr size_t OFF_DOTS = OFF_DEN  + BN_ALL;                  // [B*EA]
static constexpr size_t OFF_W    = OFF_DOTS + (size_t)B_ * EA_;        // [B*EA]
static constexpr size_t OFF_WG_HI = OFF_W + (size_t)B_ * EA_;          // bf16 [D][D]
static constexpr size_t OFF_WG_LO = OFF_WG_HI + (size_t)D_ * D_ / 2;
static constexpr size_t OFF_WL_HI = OFF_WG_LO + (size_t)D_ * D_ / 2;
static constexpr size_t OFF_WL_LO = OFF_WL_HI + (size_t)D_ * D_ / 2;
static constexpr size_t SCRATCH_FLOATS = OFF_WL_LO + (size_t)D_ * D_ / 2;

__device__ float g_scratch[SCRATCH_FLOATS];

// ---------------- helpers -------------------------------------------------------
__device__ __forceinline__ void red_add_v4(float* p, float x, float y, float z, float w)
{
    unsigned long long g = __cvta_generic_to_global((void*)p);
    asm volatile("red.global.add.v4.f32 [%0], {%1,%2,%3,%4};"
                 :: "l"(g), "f"(x), "f"(y), "f"(z), "f"(w) : "memory");
}
__device__ __forceinline__ unsigned f32_enc(float f) {
    unsigned u = __float_as_uint(f);
    return (u & 0x80000000u) ? ~u : (u | 0x80000000u);
}
__device__ __forceinline__ float f32_dec(unsigned u) {
    return (u & 0x80000000u) ? __uint_as_float(u ^ 0x80000000u) : __uint_as_float(~u);
}
__device__ __forceinline__ unsigned long long pack2(float x, float y) {
    unsigned long long r;
    asm("mov.b64 %0, {%1, %2};" : "=l"(r) : "f"(x), "f"(y));
    return r;
}
__device__ __forceinline__ void unpack2(unsigned long long v, float& x, float& y) {
    asm("mov.b64 {%0, %1}, %2;" : "=f"(x), "=f"(y) : "l"(v));
}
__device__ __forceinline__ void ffma2(unsigned long long& d, unsigned long long a,
                                      unsigned long long b) {
    asm("fma.rn.f32x2 %0, %1, %2, %0;" : "+l"(d) : "l"(a), "l"(b));
}

// mma.sync m16n8k16 bf16 -> f32 (explicit PTX ISA lane mapping)
__device__ __forceinline__ void mma16816(float* c, const uint32_t* a, const uint32_t* b)
{
    asm("mma.sync.aligned.m16n8k16.row.col.f32.bf16.bf16.f32 "
        "{%0,%1,%2,%3}, {%4,%5,%6,%7}, {%8,%9}, {%0,%1,%2,%3};"
        : "+f"(c[0]), "+f"(c[1]), "+f"(c[2]), "+f"(c[3])
        : "r"(a[0]), "r"(a[1]), "r"(a[2]), "r"(a[3]), "r"(b[0]), "r"(b[1]));
}

// split two fp32 into packed bf16-hi and bf16-lo words
__device__ __forceinline__ void split2(float2 x, uint32_t& h, uint32_t& l)
{
    __nv_bfloat16 h0 = __float2bfloat16_rn(x.x);
    __nv_bfloat16 h1 = __float2bfloat16_rn(x.y);
    __nv_bfloat16 l0 = __float2bfloat16_rn(x.x - __bfloat162float(h0));
    __nv_bfloat16 l1 = __float2bfloat16_rn(x.y - __bfloat162float(h1));
    h = (uint32_t)__bfloat16_as_ushort(h0) | ((uint32_t)__bfloat16_as_ushort(h1) << 16);
    l = (uint32_t)__bfloat16_as_ushort(l0) | ((uint32_t)__bfloat16_as_ushort(l1) << 16);
}

// ---------------- weight transpose + hi/lo split ----------------------------------
// in: W[K][Ncols] fp32 ; out: hi/lo[Ncols][K] bf16
__global__ void wsplit_k(const float* __restrict__ W, int K, int Ncols,
                         __nv_bfloat16* __restrict__ hi, __nv_bfloat16* __restrict__ lo)
{
    int idx = blockIdx.x * blockDim.x + threadIdx.x;
    if (idx >= K * Ncols) return;
    int n = idx / K;
    int k = idx - n * K;
    float x = __ldg(W + (size_t)k * Ncols + n);
    __nv_bfloat16 h = __float2bfloat16_rn(x);
    float r = x - __bfloat162float(h);
    hi[idx] = h;
    lo[idx] = __float2bfloat16_rn(r);
}

// ---------------- register-direct mma.sync bf16-split GEMM ------------------------
// C = A[Mrows,512]_f32 @ Bt[512_cols... Bt: [Ncols][512] bf16 hi/lo]^T, raw store.
// NO shared memory: every fragment register is loaded directly from global with
// explicitly computed (row, col) addresses per the PTX ISA m16n8k16 lane mapping.
// Block: 256 thr = 8 warps as 4x2; warp tile 32x32 (mi=2 x16, ni=4 x8). Tile 128x64.
__global__ void __launch_bounds__(256)
gemm_mma_reg(int Mrows, int Ncols,
             const float* __restrict__ A,
             const __nv_bfloat16* __restrict__ Bhi,
             const __nv_bfloat16* __restrict__ Blo,
             float* __restrict__ C)
{
    constexpr int K = 512;
    const int tid  = threadIdx.x;
    const int wid  = tid >> 5;
    const int lane = tid & 31;
    const int g    = lane >> 2;     // group 0..7
    const int t    = lane & 3;      // thread-in-group 0..3
    const int wm   = wid >> 1;      // 0..3 (row band of 32)
    const int wn   = wid & 1;       // 0..1 (col band of 32)
    const int row0 = blockIdx.x * 128 + wm * 32;
    const int col0 = blockIdx.y * 64 + wn * 32;

    float c[2][4][4];
#pragma unroll
    for (int mi = 0; mi < 2; mi++)
#pragma unroll
        for (int ni = 0; ni < 4; ni++)
#pragma unroll
            for (int r = 0; r < 4; r++) c[mi][ni][r] = 0.f;

    for (int k0 = 0; k0 < K; k0 += 16) {
        // ---- A fragments (row-major m16k16): a0=(g,2t) a1=(g+8,2t) a2=(g,2t+8) a3=(g+8,2t+8)
        uint32_t ah[2][4], al[2][4];
#pragma unroll
        for (int mi = 0; mi < 2; mi++) {
            const float* a0 = A + (size_t)(row0 + mi * 16 + g) * K + k0 + 2 * t;
            const float* a1 = a0 + (size_t)8 * K;
            float2 x0 = *reinterpret_cast<const float2*>(a0);
            float2 x1 = *reinterpret_cast<const float2*>(a1);
            float2 x2 = *reinterpret_cast<const float2*>(a0 + 8);
            float2 x3 = *reinterpret_cast<const float2*>(a1 + 8);
            split2(x0, ah[mi][0], al[mi][0]);
            split2(x1, ah[mi][1], al[mi][1]);
            split2(x2, ah[mi][2], al[mi][2]);
            split2(x3, ah[mi][3], al[mi][3]);
        }
        // ---- B fragments (col-major k16n8): b0=(k=2t..2t+1, n=g) b1=(k=2t+8.., n=g)
        uint32_t bh[4][2], bl[4][2];
#pragma unroll
        for (int ni = 0; ni < 4; ni++) {
            size_t off = (size_t)(col0 + ni * 8 + g) * K + k0 + 2 * t;
            bh[ni][0] = *reinterpret_cast<const uint32_t*>(Bhi + off);
            bh[ni][1] = *reinterpret_cast<const uint32_t*>(Bhi + off + 8);
            bl[ni][0] = *reinterpret_cast<const uint32_t*>(Blo + off);
            bl[ni][1] = *reinterpret_cast<const uint32_t*>(Blo + off + 8);
        }
        // ---- 3-product bf16 split accumulate ----
#pragma unroll
        for (int mi = 0; mi < 2; mi++)
#pragma unroll
            for (int ni = 0; ni < 4; ni++) {
                mma16816(c[mi][ni], ah[mi], bh[ni]);
                mma16816(c[mi][ni], ah[mi], bl[ni]);
                mma16816(c[mi][ni], al[mi], bh[ni]);
            }
    }

    // ---- store: c0,c1 -> (g, 2t..2t+1); c2,c3 -> (g+8, 2t..2t+1)
#pragma unroll
    for (int mi = 0; mi < 2; mi++) {
        int r = row0 + mi * 16 + g;
#pragma unroll
        for (int ni = 0; ni < 4; ni++) {
            int cc = col0 + ni * 8 + 2 * t;
            float2 v0; v0.x = c[mi][ni][0]; v0.y = c[mi][ni][1];
            float2 v1; v1.x = c[mi][ni][2]; v1.y = c[mi][ni][3];
            *reinterpret_cast<float2*>(C + (size_t)r * Ncols + cc) = v0;
            *reinterpret_cast<float2*>(C + (size_t)(r + 8) * Ncols + cc) = v1;
        }
    }
}

// ---------------- FFMA2 double-buffered SGEMM (proven, q/k path) ------------------
template <int BM, int BN, int BK, int TM, int TN>
__global__ void __launch_bounds__((BM / TM) * (BN / TN))
sgemm_k(int Mrows, int Ncols, int K,
        const float* __restrict__ A,
        const float* __restrict__ Bm,
        const float* __restrict__ bias,
        const float* __restrict__ resid,
        const float* __restrict__ gate,
        float* __restrict__ C)
{
    constexpr int THREADS = (BM / TM) * (BN / TN);
    constexpr int PAD = 4;
    constexpr int NA = (BM * BK) / (4 * THREADS);
    constexpr int NB = (BK * BN) / (4 * THREADS);
    static_assert(NA >= 1 && NB >= 1, "tile/thread mismatch");

    __shared__ __align__(16) float As[2][BK][BM + PAD];
    __shared__ __align__(16) float Bs[2][BK][BN + PAD];

    const int tid = threadIdx.x;
    const int block_row = blockIdx.x * BM;
    const int block_col = blockIdx.y * BN;
    const int tx = tid % (BN / TN);
    const int ty = tid / (BN / TN);

    unsigned long long acc[TM][TN / 2];
#pragma unroll
    for (int i = 0; i < TM; i++)
#pragma unroll
        for (int j = 0; j < TN / 2; j++) acc[i][j] = 0ull;

    float4 ar[NA], br[NB];
#pragma unroll
    for (int u = 0; u < NA; u++) {
        int i  = tid + u * THREADS;
        int r  = i / (BK / 4);
        int c4 = (i % (BK / 4)) * 4;
        ar[u] = *reinterpret_cast<const float4*>(A + (size_t)(block_row + r) * K + c4);
    }
#pragma unroll
    for (int u = 0; u < NB; u++) {
        int i  = tid + u * THREADS;
        int r  = i / (BN / 4);
        int c4 = (i % (BN / 4)) * 4;
        br[u] = *reinterpret_cast<const float4*>(Bm + (size_t)r * Ncols + block_col + c4);
    }

    int buf = 0;
    for (int k0 = 0; k0 < K; k0 += BK) {
#pragma unroll
        for (int u = 0; u < NA; u++) {
            int i  = tid + u * THREADS;
            int r  = i / (BK / 4);
            int c4 = (i % (BK / 4)) * 4;
            As[buf][c4 + 0][r] = ar[u].x;
            As[buf][c4 + 1][r] = ar[u].y;
            As[buf][c4 + 2][r] = ar[u].z;
            As[buf][c4 + 3][r] = ar[u].w;
        }
#pragma unroll
        for (int u = 0; u < NB; u++) {
            int i  = tid + u * THREADS;
            int r  = i / (BN / 4);
            int c4 = (i % (BN / 4)) * 4;
            *reinterpret_cast<float4*>(&Bs[buf][r][c4]) = br[u];
        }
        __syncthreads();

        if (k0 + BK < K) {
#pragma unroll
            for (int u = 0; u < NA; u++) {
                int i  = tid + u * THREADS;
                int r  = i / (BK / 4);
                int c4 = (i % (BK / 4)) * 4;
                ar[u] = *reinterpret_cast<const float4*>(A + (size_t)(block_row + r) * K + k0 + BK + c4);
            }
#pragma unroll
            for (int u = 0; u < NB; u++) {
                int i  = tid + u * THREADS;
                int r  = i / (BN / 4);
                int c4 = (i % (BN / 4)) * 4;
                br[u] = *reinterpret_cast<const float4*>(Bm + (size_t)(k0 + BK + r) * Ncols + block_col + c4);
            }
        }

#pragma unroll
        for (int kk = 0; kk < BK; kk++) {
            const float* arow = &As[buf][kk][ty * TM];
            float4 a0 = *reinterpret_cast<const float4*>(arow);
            float4 a1 = *reinterpret_cast<const float4*>(arow + 4);
            ulonglong2 b01 = *reinterpret_cast<const ulonglong2*>(&Bs[buf][kk][tx * TN]);
            ulonglong2 b23 = *reinterpret_cast<const ulonglong2*>(&Bs[buf][kk][tx * TN + 4]);
            unsigned long long bp[4] = { b01.x, b01.y, b23.x, b23.y };
            unsigned long long ad[TM];
            ad[0] = pack2(a0.x, a0.x); ad[1] = pack2(a0.y, a0.y);
            ad[2] = pack2(a0.z, a0.z); ad[3] = pack2(a0.w, a0.w);
            ad[4] = pack2(a1.x, a1.x); ad[5] = pack2(a1.y, a1.y);
            ad[6] = pack2(a1.z, a1.z); ad[7] = pack2(a1.w, a1.w);
#pragma unroll
            for (int i = 0; i < TM; i++)
#pragma unroll
                for (int j = 0; j < TN / 2; j++)
                    ffma2(acc[i][j], ad[i], bp[j]);
        }
        buf ^= 1;
        __syncthreads();
    }

    const float g = gate ? tanhf(gate[0]) : 0.f;
#pragma unroll
    for (int i = 0; i < TM; i++) {
        int r = block_row + ty * TM + i;
#pragma unroll
        for (int j = 0; j < TN / 2; j++) {
            int cc = block_col + tx * TN + 2 * j;
            float lo, hi;
            unpack2(acc[i][j], lo, hi);
            if (bias) { lo += __ldg(bias + cc); hi += __ldg(bias + cc + 1); }
            if (resid) {
                float2 rv = *reinterpret_cast<const float2*>(resid + (size_t)r * Ncols + cc);
                lo = rv.x + g * lo;
                hi = rv.y + g * hi;
            }
            float2 ov; ov.x = lo; ov.y = hi;
            *reinterpret_cast<float2*>(C + (size_t)r * Ncols + cc) = ov;
        }
    }
}

// ---------------- batched elementwise / scatter kernels --------------------------
__global__ void init_k(float* __restrict__ deg, unsigned* __restrict__ menc,
                       float* __restrict__ den, float* __restrict__ gatt)
{
    int i = blockIdx.x * blockDim.x + threadIdx.x;
    if (i < (int)((size_t)BN_ALL * D_ / 4)) reinterpret_cast<float4*>(gatt)[i] = make_float4(0.f, 0.f, 0.f, 0.f);
    if (i < BM_ALL) deg[i] = 1.0f;
    if (i < BN_ALL) { menc[i] = 0u; den[i] = 0.f; }
}

__global__ void deg_add_k(const int* __restrict__ ei_all, float* __restrict__ deg)
{
    int i = blockIdx.x * blockDim.x + threadIdx.x;
    if (i >= B_ * EG_) return;
    int b = i >> 16;
    int e = i & (EG_ - 1);
    int d = __ldg(ei_all + (size_t)b * 2 * EG_ + EG_ + e);
    atomicAdd(deg + b * M_ + d, 1.0f);
}

__global__ void gcn_self_k(const float* __restrict__ tw, const float* __restrict__ deg,
                           const int* __restrict__ t2e_all, const float* __restrict__ bg,
                           float* __restrict__ edge)
{
    int idx = blockIdx.x * blockDim.x + threadIdx.x;
    if (idx >= BM_ALL * (D_ / 4)) return;
    int mg = idx >> 7;
    int j  = (idx & 127) << 2;
    int b  = mg >> 14;
    int m  = mg & (M_ - 1);
    float c = 1.0f / __ldg(deg + mg);
    int trow = __ldg(t2e_all + (size_t)b * M_ + m);
    float4 v = *reinterpret_cast<const float4*>(tw + ((size_t)b * N_ + trow) * D_ + j);
    float4 bb = *reinterpret_cast<const float4*>(bg + j);
    float4 o;
    o.x = bb.x + c * v.x; o.y = bb.y + c * v.y; o.z = bb.z + c * v.z; o.w = bb.w + c * v.w;
    *reinterpret_cast<float4*>(edge + (size_t)mg * D_ + j) = o;
}

__global__ void gcn_scatter_k(const float* __restrict__ tw, const float* __restrict__ deg,
                              const int* __restrict__ t2e_all, const int* __restrict__ ei_all,
                              float* __restrict__ edge)
{
    int idx = blockIdx.x * blockDim.x + threadIdx.x;
    if (idx >= B_ * EG_ * (D_ / 4)) return;
    int eg = idx >> 7;
    int j  = (idx & 127) << 2;
    int b  = eg >> 16;
    int e  = eg & (EG_ - 1);
    const int* ei = ei_all + (size_t)b * 2 * EG_;
    int s = __ldg(ei + e), d = __ldg(ei + EG_ + e);
    float c = rsqrtf(__ldg(deg + b * M_ + s)) * rsqrtf(__ldg(deg + b * M_ + d));
    int trow = __ldg(t2e_all + (size_t)b * M_ + s);
    float4 v = *reinterpret_cast<const float4*>(tw + ((size_t)b * N_ + trow) * D_ + j);
    red_add_v4(edge + ((size_t)b * M_ + d) * D_ + j, c * v.x, c * v.y, c * v.z, c * v.w);
}

__global__ void att_dot_k(const float* __restrict__ q, const float* __restrict__ k,
                          const int* __restrict__ es_all, const int* __restrict__ ed_all,
                          float* __restrict__ dots, unsigned* __restrict__ menc)
{
    int eg = (blockIdx.x * blockDim.x + threadIdx.x) >> 5;
    int lane = threadIdx.x & 31;
    if (eg >= B_ * EA_) return;
    int b = eg >> 16;
    int e = eg & (EA_ - 1);
    int s = __ldg(es_all + (size_t)b * EA_ + e);
    int d = __ldg(ed_all + (size_t)b * EA_ + e);
    const float* qp = q + ((size_t)b * N_ + d) * DK_;
    const float* kp = k + ((size_t)b * M_ + s) * DK_;
    float v = qp[lane] * kp[lane] + qp[lane + 32] * kp[lane + 32];
#pragma unroll
    for (int off = 16; off; off >>= 1) v += __shfl_xor_sync(0xFFFFFFFFu, v, off);
    if (lane == 0) {
        v *= 0.125f;
        dots[eg] = v;
        atomicMax(&menc[b * N_ + d], f32_enc(v));
    }
}

__global__ void att_w_k(const float* __restrict__ dots, const unsigned* __restrict__ menc,
                        const int* __restrict__ ed_all, float* __restrict__ w,
                        float* __restrict__ den)
{
    int eg = blockIdx.x * blockDim.x + threadIdx.x;
    if (eg >= B_ * EA_) return;
    int b = eg >> 16;
    int e = eg & (EA_ - 1);
    int d = __ldg(ed_all + (size_t)b * EA_ + e);
    float m = f32_dec(menc[b * N_ + d]);
    if (!isfinite(m)) m = 0.f;
    float wv = __expf(fminf(dots[eg] - m, 0.f));
    w[eg] = wv;
    atomicAdd(&den[b * N_ + d], wv);
}

__global__ void att_scatter_k(const float* __restrict__ w, const float* __restrict__ den,
                              const float* __restrict__ edge,
                              const int* __restrict__ es_all, const int* __restrict__ ed_all,
                              float* __restrict__ gatt)
{
    int idx = blockIdx.x * blockDim.x + threadIdx.x;
    if (idx >= B_ * EA_ * (D_ / 4)) return;
    int eg = idx >> 7;
    int j  = (idx & 127) << 2;
    int b  = eg >> 16;
    int e  = eg & (EA_ - 1);
    int s = __ldg(es_all + (size_t)b * EA_ + e);
    int d = __ldg(ed_all + (size_t)b * EA_ + e);
    float dn = __ldg(den + b * N_ + d);
    float sc = __ldg(w + eg) / (dn > 0.f ? dn : 1.f);
    float4 v = *reinterpret_cast<const float4*>(edge + ((size_t)b * M_ + s) * D_ + j);
    red_add_v4(gatt + ((size_t)b * N_ + d) * D_ + j, sc * v.x, sc * v.y, sc * v.z, sc * v.w);
}

__global__ void new1_k(const float* __restrict__ tok, const float* __restrict__ gatt,
                       const float* __restrict__ ga, float* __restrict__ out)
{
    int idx = blockIdx.x * blockDim.x + threadIdx.x;
    if (idx >= (int)((size_t)BN_ALL * D_ / 4)) return;
    float g = tanhf(ga[0]);
    float4 t = reinterpret_cast<const float4*>(tok)[idx];
    float4 a = reinterpret_cast<const float4*>(gatt)[idx];
    float4 o;
    o.x = t.x + g * a.x; o.y = t.y + g * a.y; o.z = t.z + g * a.z; o.w = t.w + g * a.w;
    reinterpret_cast<float4*>(out)[idx] = o;
}

// out = resid + tanh(gate) * (x + bias)
__global__ void epi_k(const float* __restrict__ x, const float* __restrict__ bias,
                      const float* __restrict__ resid, const float* __restrict__ gate,
                      float* __restrict__ out)
{
    int idx = blockIdx.x * blockDim.x + threadIdx.x;
    if (idx >= (int)((size_t)BN_ALL * D_ / 4)) return;
    int c = (idx & 127) << 2;
    float g = tanhf(gate[0]);
    float4 v = reinterpret_cast<const float4*>(x)[idx];
    float4 b = *reinterpret_cast<const float4*>(bias + c);
    float4 r = reinterpret_cast<const float4*>(resid)[idx];
    float4 o;
    o.x = r.x + g * (v.x + b.x); o.y = r.y + g * (v.y + b.y);
    o.z = r.z + g * (v.z + b.z); o.w = r.w + g * (v.w + b.w);
    reinterpret_cast<float4*>(out)[idx] = o;
}

// ---------------- launch ----------------------------------------------------------
extern "C" void kernel_launch(void* const* d_in, const int* in_sizes, int n_in,
                              void* d_out, int out_size)
{
    (void)in_sizes; (void)n_in; (void)out_size;

    const float* tok = (const float*)d_in[0];
    const int*   t2e = (const int*)d_in[1];
    const int*   ei  = (const int*)d_in[2];
    const int*   aes = (const int*)d_in[3];
    const int*   aed = (const int*)d_in[4];
    const float* Wg = (const float*)d_in[5];
    const float* bg = (const float*)d_in[6];
    const float* Wk = (const float*)d_in[7];
    const float* bk = (const float*)d_in[8];
    const float* Wq = (const float*)d_in[9];
    const float* bq = (const float*)d_in[10];
    const float* Wl = (const float*)d_in[11];
    const float* bl = (const float*)d_in[12];
    const float* ga = (const float*)d_in[13];
    const float* gb = (const float*)d_in[14];
    float* out = (float*)d_out;

    float* base = nullptr;
    cudaGetSymbolAddress((void**)&base, g_scratch);

    float*    tw   = base + OFF_TW;
    float*    edge = base + OFF_EDGE;
    float*    kbuf = base + OFF_K;
    float*    qbuf = base + OFF_Q;
    float*    new1 = base + OFF_NEW1;
    float*    gatt = base + OFF_GATT;
    float*    deg  = base + OFF_DEG;
    unsigned* menc = (unsigned*)(base + OFF_MENC);
    float*    den  = base + OFF_DEN;
    float*    dots = base + OFF_DOTS;
    float*    wbuf = base + OFF_W;
    __nv_bfloat16* wg_hi = (__nv_bfloat16*)(base + OFF_WG_HI);
    __nv_bfloat16* wg_lo = (__nv_bfloat16*)(base + OFF_WG_LO);
    __nv_bfloat16* wl_hi = (__nv_bfloat16*)(base + OFF_WL_HI);
    __nv_bfloat16* wl_lo = (__nv_bfloat16*)(base + OFF_WL_LO);

    const int T = 256;

    // weight prep (transpose + hi/lo split) — big GEMM weights only
    wsplit_k<<<(D_ * D_ + T - 1) / T, T>>>(Wg, D_, D_, wg_hi, wg_lo);
    wsplit_k<<<(D_ * D_ + T - 1) / T, T>>>(Wl, D_, D_, wl_hi, wl_lo);

    init_k<<<(int)(((size_t)BN_ALL * D_ / 4 + T - 1) / T), T>>>(deg, menc, den, gatt);

    // tw = tok @ Wg  (register-direct mma.sync bf16-split, raw store)
    gemm_mma_reg<<<dim3(BN_ALL / 128, D_ / 64), 256>>>(BN_ALL, D_, tok, wg_hi, wg_lo, tw);

    // q = tok @ Wq + bq  (proven FFMA path)
    sgemm_k<128, 64, 16, 8, 8><<<dim3(BN_ALL / 128, 1), 128>>>(
        BN_ALL, DK_, D_, tok, Wq, bq, nullptr, nullptr, qbuf);

    deg_add_k<<<(B_ * EG_ + T - 1) / T, T>>>(ei, deg);
    gcn_self_k<<<(BM_ALL * (D_ / 4) + T - 1) / T, T>>>(tw, deg, t2e, bg, edge);
    gcn_scatter_k<<<(int)(((size_t)B_ * EG_ * (D_ / 4) + T - 1) / T), T>>>(tw, deg, t2e, ei, edge);

    // k = edge @ Wk + bk  (proven FFMA path)
    sgemm_k<128, 64, 16, 8, 8><<<dim3(BM_ALL / 128, 1), 128>>>(
        BM_ALL, DK_, D_, edge, Wk, bk, nullptr, nullptr, kbuf);

    att_dot_k<<<(int)(((size_t)B_ * EA_ * 32 + T - 1) / T), T>>>(qbuf, kbuf, aes, aed, dots, menc);
    att_w_k<<<(B_ * EA_ + T - 1) / T, T>>>(dots, menc, aed, wbuf, den);
    att_scatter_k<<<(int)(((size_t)B_ * EA_ * (D_ / 4) + T - 1) / T), T>>>(wbuf, den, edge, aes, aed, gatt);

    new1_k<<<(int)(((size_t)BN_ALL * D_ / 4 + T - 1) / T), T>>>(tok, gatt, ga, new1);

    // raw = new1 @ Wl (into dead `edge` buffer), then out = new1 + tanh(gb)*(raw + bl)
    gemm_mma_reg<<<dim3(BN_ALL / 128, D_ / 64), 256>>>(BN_ALL, D_, new1, wl_hi, wl_lo, edge);
    epi_k<<<(int)(((size_t)BN_ALL * D_ / 4 + T - 1) / T), T>>>(edge, bl, new1, gb, out);
}

// round 9
// speedup vs baseline: 3.4185x; 1.3866x over previous
#include <cuda_runtime.h>
#include <cuda_bf16.h>
#include <cstdint>
#include <math.h>

// Problem constants (CausalMessagePassingLayer_90237262889057)
static constexpr int B_  = 4;
static constexpr int N_  = 4096;
static constexpr int M_  = 16384;
static constexpr int EG_ = 65536;
static constexpr int EA_ = 65536;
static constexpr int D_  = 512;
static constexpr int DK_ = 64;

static constexpr int BN_ALL = B_ * N_;   // 16384
static constexpr int BM_ALL = B_ * M_;   // 65536

// ---------------- scratch pool (floats; all offsets multiples of 4 => 16B aligned) --
static constexpr size_t OFF_TW   = 0;                                  // [B*N, D] f32
static constexpr size_t OFF_EDGE = OFF_TW   + (size_t)BN_ALL * D_;     // [B*M, D] f32
static constexpr size_t OFF_K    = OFF_EDGE + (size_t)BM_ALL * D_;     // [B*M, DK]
static constexpr size_t OFF_Q    = OFF_K    + (size_t)BM_ALL * DK_;    // [B*N, DK]
static constexpr size_t OFF_NEW1 = OFF_Q    + (size_t)BN_ALL * DK_;    // [B*N, D]
static constexpr size_t OFF_GATT = OFF_NEW1 + (size_t)BN_ALL * D_;     // [B*N, D]
static constexpr size_t OFF_DEG  = OFF_GATT + (size_t)BN_ALL * D_;     // [B*M]
static constexpr size_t OFF_MENC = OFF_DEG  + BM_ALL;                  // [B*N]
static constexpr size_t OFF_DEN  = OFF_MENC + BN_ALL;                  // [B*N]
static constexpr size_t OFF_DOTS = OFF_DEN  + BN_ALL;                  // [B*EA]
static constexpr size_t OFF_W    = OFF_DOTS + (size_t)B_ * EA_;        // [B*EA]
// packed operands (fragment-major). float counts = uint4 count * 4.
static constexpr size_t TOKP_F   = (size_t)(BN_ALL / 16) * 32 * 2 * 32 * 4;   // 8.4M
static constexpr size_t EDGEP_F  = (size_t)(BM_ALL / 16) * 32 * 2 * 32 * 4;   // 33.5M
static constexpr size_t WBIG_F   = (size_t)(D_ / 8) * 32 * 32 * 4;            // 262144
static constexpr size_t WSML_F   = (size_t)(DK_ / 8) * 32 * 32 * 4;           // 32768
static constexpr size_t OFF_TOKP = OFF_W + (size_t)B_ * EA_;
static constexpr size_t OFF_EDGEP= OFF_TOKP + TOKP_F;
static constexpr size_t OFF_N1P  = OFF_EDGEP + EDGEP_F;
static constexpr size_t OFF_WGP  = OFF_N1P + TOKP_F;
static constexpr size_t OFF_WLP  = OFF_WGP + WBIG_F;
static constexpr size_t OFF_WKP  = OFF_WLP + WBIG_F;
static constexpr size_t OFF_WQP  = OFF_WKP + WSML_F;
static constexpr size_t SCRATCH_FLOATS = OFF_WQP + WSML_F;

__device__ __align__(16) float g_scratch[SCRATCH_FLOATS];

// ---------------- helpers -------------------------------------------------------
__device__ __forceinline__ void red_add_v4(float* p, float x, float y, float z, float w)
{
    unsigned long long g = __cvta_generic_to_global((void*)p);
    asm volatile("red.global.add.v4.f32 [%0], {%1,%2,%3,%4};"
                 :: "l"(g), "f"(x), "f"(y), "f"(z), "f"(w) : "memory");
}
__device__ __forceinline__ unsigned f32_enc(float f) {
    unsigned u = __float_as_uint(f);
    return (u & 0x80000000u) ? ~u : (u | 0x80000000u);
}
__device__ __forceinline__ float f32_dec(unsigned u) {
    return (u & 0x80000000u) ? __uint_as_float(u ^ 0x80000000u) : __uint_as_float(~u);
}

// mma.sync m16n8k16 bf16 -> f32 (explicit PTX ISA lane mapping) — PROVEN round 8
__device__ __forceinline__ void mma16816(float* c, const uint32_t* a, const uint32_t* b)
{
    asm("mma.sync.aligned.m16n8k16.row.col.f32.bf16.bf16.f32 "
        "{%0,%1,%2,%3}, {%4,%5,%6,%7}, {%8,%9}, {%0,%1,%2,%3};"
        : "+f"(c[0]), "+f"(c[1]), "+f"(c[2]), "+f"(c[3])
        : "r"(a[0]), "r"(a[1]), "r"(a[2]), "r"(a[3]), "r"(b[0]), "r"(b[1]));
}

// split two fp32 into packed bf16-hi and bf16-lo words — PROVEN round 8
__device__ __forceinline__ void split2(float2 x, uint32_t& h, uint32_t& l)
{
    __nv_bfloat16 h0 = __float2bfloat16_rn(x.x);
    __nv_bfloat16 h1 = __float2bfloat16_rn(x.y);
    __nv_bfloat16 l0 = __float2bfloat16_rn(x.x - __bfloat162float(h0));
    __nv_bfloat16 l1 = __float2bfloat16_rn(x.y - __bfloat162float(h1));
    h = (uint32_t)__bfloat16_as_ushort(h0) | ((uint32_t)__bfloat16_as_ushort(h1) << 16);
    l = (uint32_t)__bfloat16_as_ushort(l0) | ((uint32_t)__bfloat16_as_ushort(l1) << 16);
}

// ---------------- operand packing --------------------------------------------------
// Weights: W[K=512][N] fp32 -> Bp[N/8][32 ks][32 lane] uint4 {b0h, b1h, b0l, b1l}
// where lane l: g=l>>2, t=l&3; n = nc*8+g; b0 = W[ks*16+2t .. +1][n], b1 = +8.
__global__ void wpack_k(const float* __restrict__ W, int Ncols, uint4* __restrict__ Bp)
{
    int idx = blockIdx.x * blockDim.x + threadIdx.x;
    if (idx >= (Ncols / 8) * 1024) return;
    int nc   = idx >> 10;
    int ks   = (idx >> 5) & 31;
    int lane = idx & 31;
    int g = lane >> 2, t = lane & 3;
    int n = nc * 8 + g;
    int k = ks * 16 + 2 * t;
    float2 w0 = make_float2(__ldg(W + (size_t)k * Ncols + n),
                            __ldg(W + (size_t)(k + 1) * Ncols + n));
    float2 w1 = make_float2(__ldg(W + (size_t)(k + 8) * Ncols + n),
                            __ldg(W + (size_t)(k + 9) * Ncols + n));
    uint32_t b0h, b0l, b1h, b1l;
    split2(w0, b0h, b0l);
    split2(w1, b1h, b1l);
    Bp[idx] = make_uint4(b0h, b1h, b0l, b1l);
}

// Activations: A[M][512] fp32 -> Ap[M/16][32 ks][2 h][32 lane] uint4
// lane l: g=l>>2, t=l&3; a0=(rb*16+g, ks*16+2t..+1) a1=row+8 a2=k+8 a3=row+8,k+8
__global__ void apack_k(const float* __restrict__ A, int Mrows, uint4* __restrict__ Ap)
{
    int idx = blockIdx.x * blockDim.x + threadIdx.x;
    if (idx >= (Mrows / 16) * 1024) return;
    int rb   = idx >> 10;
    int ks   = (idx >> 5) & 31;
    int lane = idx & 31;
    int g = lane >> 2, t = lane & 3;
    int row = rb * 16 + g;
    int k = ks * 16 + 2 * t;
    const float* p0 = A + (size_t)row * D_ + k;
    const float* p1 = A + (size_t)(row + 8) * D_ + k;
    float2 x0 = *reinterpret_cast<const float2*>(p0);
    float2 x1 = *reinterpret_cast<const float2*>(p1);
    float2 x2 = *reinterpret_cast<const float2*>(p0 + 8);
    float2 x3 = *reinterpret_cast<const float2*>(p1 + 8);
    uint32_t a0h, a0l, a1h, a1l, a2h, a2l, a3h, a3l;
    split2(x0, a0h, a0l);
    split2(x1, a1h, a1l);
    split2(x2, a2h, a2l);
    split2(x3, a3h, a3l);
    size_t base = ((size_t)(rb * 32 + ks) * 2) * 32 + lane;
    Ap[base]      = make_uint4(a0h, a1h, a2h, a3h);
    Ap[base + 32] = make_uint4(a0l, a1l, a2l, a3l);
}

// ---------------- packed register-direct bf16-split MMA GEMM ----------------------
// C[Mrows,Ncols] = A @ Bt^T  (K=512 fixed). Block 128x64, 8 warps as 4x2,
// warp tile 32x32 (mi 2 x 16, ni 4 x 8). Optional bias. Raw fp32 store.
__global__ void __launch_bounds__(256)
gemm_mma_pk(int Mrows, int Ncols,
            const uint4* __restrict__ Ap,
            const uint4* __restrict__ Bp,
            const float* __restrict__ bias,
            float* __restrict__ C)
{
    const int tid  = threadIdx.x;
    const int wid  = tid >> 5;
    const int lane = tid & 31;
    const int g    = lane >> 2;
    const int t    = lane & 3;
    const int wm   = wid >> 1;      // 0..3
    const int wn   = wid & 1;       // 0..1
    const int row0 = blockIdx.x * 128 + wm * 32;
    const int col0 = blockIdx.y * 64 + wn * 32;
    const int rb0  = row0 >> 4;     // 16-row block index
    const int nc0  = col0 >> 3;     // 8-col block index

    float c[2][4][4];
#pragma unroll
    for (int mi = 0; mi < 2; mi++)
#pragma unroll
        for (int ni = 0; ni < 4; ni++)
#pragma unroll
            for (int r = 0; r < 4; r++) c[mi][ni][r] = 0.f;

#pragma unroll 4
    for (int ks = 0; ks < 32; ks++) {
        uint32_t ah[2][4], al[2][4];
#pragma unroll
        for (int mi = 0; mi < 2; mi++) {
            size_t base = ((size_t)((rb0 + mi) * 32 + ks) * 2) * 32 + lane;
            uint4 h4 = __ldg(Ap + base);
            uint4 l4 = __ldg(Ap + base + 32);
            ah[mi][0] = h4.x; ah[mi][1] = h4.y; ah[mi][2] = h4.z; ah[mi][3] = h4.w;
            al[mi][0] = l4.x; al[mi][1] = l4.y; al[mi][2] = l4.z; al[mi][3] = l4.w;
        }
#pragma unroll
        for (int ni = 0; ni < 4; ni++) {
            uint4 b4 = __ldg(Bp + (size_t)((nc0 + ni) * 32 + ks) * 32 + lane);
            uint32_t bh[2] = { b4.x, b4.y };
            uint32_t bl[2] = { b4.z, b4.w };
#pragma unroll
            for (int mi = 0; mi < 2; mi++) {
                mma16816(c[mi][ni], ah[mi], bh);
                mma16816(c[mi][ni], ah[mi], bl);
                mma16816(c[mi][ni], al[mi], bh);
            }
        }
    }

    // store: c0,c1 -> (g, 2t..2t+1); c2,c3 -> (g+8, 2t..2t+1)
#pragma unroll
    for (int mi = 0; mi < 2; mi++) {
        int r = row0 + mi * 16 + g;
#pragma unroll
        for (int ni = 0; ni < 4; ni++) {
            int cc = col0 + ni * 8 + 2 * t;
            float bx = 0.f, by = 0.f;
            if (bias) { bx = __ldg(bias + cc); by = __ldg(bias + cc + 1); }
            float2 v0; v0.x = c[mi][ni][0] + bx; v0.y = c[mi][ni][1] + by;
            float2 v1; v1.x = c[mi][ni][2] + bx; v1.y = c[mi][ni][3] + by;
            *reinterpret_cast<float2*>(C + (size_t)r * Ncols + cc) = v0;
            *reinterpret_cast<float2*>(C + (size_t)(r + 8) * Ncols + cc) = v1;
        }
    }
}

// ---------------- batched elementwise / scatter kernels --------------------------
__global__ void init_k(float* __restrict__ deg, unsigned* __restrict__ menc,
                       float* __restrict__ den, float* __restrict__ gatt)
{
    int i = blockIdx.x * blockDim.x + threadIdx.x;
    if (i < (int)((size_t)BN_ALL * D_ / 4)) reinterpret_cast<float4*>(gatt)[i] = make_float4(0.f, 0.f, 0.f, 0.f);
    if (i < BM_ALL) deg[i] = 1.0f;
    if (i < BN_ALL) { menc[i] = 0u; den[i] = 0.f; }
}

__global__ void deg_add_k(const int* __restrict__ ei_all, float* __restrict__ deg)
{
    int i = blockIdx.x * blockDim.x + threadIdx.x;
    if (i >= B_ * EG_) return;
    int b = i >> 16;
    int e = i & (EG_ - 1);
    int d = __ldg(ei_all + (size_t)b * 2 * EG_ + EG_ + e);
    atomicAdd(deg + b * M_ + d, 1.0f);
}

__global__ void gcn_self_k(const float* __restrict__ tw, const float* __restrict__ deg,
                           const int* __restrict__ t2e_all, const float* __restrict__ bg,
                           float* __restrict__ edge)
{
    int idx = blockIdx.x * blockDim.x + threadIdx.x;
    if (idx >= BM_ALL * (D_ / 4)) return;
    int mg = idx >> 7;
    int j  = (idx & 127) << 2;
    int b  = mg >> 14;
    int m  = mg & (M_ - 1);
    float c = 1.0f / __ldg(deg + mg);
    int trow = __ldg(t2e_all + (size_t)b * M_ + m);
    float4 v = *reinterpret_cast<const float4*>(tw + ((size_t)b * N_ + trow) * D_ + j);
    float4 bb = *reinterpret_cast<const float4*>(bg + j);
    float4 o;
    o.x = bb.x + c * v.x; o.y = bb.y + c * v.y; o.z = bb.z + c * v.z; o.w = bb.w + c * v.w;
    *reinterpret_cast<float4*>(edge + (size_t)mg * D_ + j) = o;
}

__global__ void gcn_scatter_k(const float* __restrict__ tw, const float* __restrict__ deg,
                              const int* __restrict__ t2e_all, const int* __restrict__ ei_all,
                              float* __restrict__ edge)
{
    int idx = blockIdx.x * blockDim.x + threadIdx.x;
    if (idx >= B_ * EG_ * (D_ / 4)) return;
    int eg = idx >> 7;
    int j  = (idx & 127) << 2;
    int b  = eg >> 16;
    int e  = eg & (EG_ - 1);
    const int* ei = ei_all + (size_t)b * 2 * EG_;
    int s = __ldg(ei + e), d = __ldg(ei + EG_ + e);
    float c = rsqrtf(__ldg(deg + b * M_ + s)) * rsqrtf(__ldg(deg + b * M_ + d));
    int trow = __ldg(t2e_all + (size_t)b * M_ + s);
    float4 v = *reinterpret_cast<const float4*>(tw + ((size_t)b * N_ + trow) * D_ + j);
    red_add_v4(edge + ((size_t)b * M_ + d) * D_ + j, c * v.x, c * v.y, c * v.z, c * v.w);
}

__global__ void att_dot_k(const float* __restrict__ q, const float* __restrict__ k,
                          const int* __restrict__ es_all, const int* __restrict__ ed_all,
                          float* __restrict__ dots, unsigned* __restrict__ menc)
{
    int eg = (blockIdx.x * blockDim.x + threadIdx.x) >> 5;
    int lane = threadIdx.x & 31;
    if (eg >= B_ * EA_) return;
    int b = eg >> 16;
    int e = eg & (EA_ - 1);
    int s = __ldg(es_all + (size_t)b * EA_ + e);
    int d = __ldg(ed_all + (size_t)b * EA_ + e);
    const float* qp = q + ((size_t)b * N_ + d) * DK_;
    const float* kp = k + ((size_t)b * M_ + s) * DK_;
    float v = qp[lane] * kp[lane] + qp[lane + 32] * kp[lane + 32];
#pragma unroll
    for (int off = 16; off; off >>= 1) v += __shfl_xor_sync(0xFFFFFFFFu, v, off);
    if (lane == 0) {
        v *= 0.125f;
        dots[eg] = v;
        atomicMax(&menc[b * N_ + d], f32_enc(v));
    }
}

__global__ void att_w_k(const float* __restrict__ dots, const unsigned* __restrict__ menc,
                        const int* __restrict__ ed_all, float* __restrict__ w,
                        float* __restrict__ den)
{
    int eg = blockIdx.x * blockDim.x + threadIdx.x;
    if (eg >= B_ * EA_) return;
    int b = eg >> 16;
    int e = eg & (EA_ - 1);
    int d = __ldg(ed_all + (size_t)b * EA_ + e);
    float m = f32_dec(menc[b * N_ + d]);
    if (!isfinite(m)) m = 0.f;
    float wv = __expf(fminf(dots[eg] - m, 0.f));
    w[eg] = wv;
    atomicAdd(&den[b * N_ + d], wv);
}

__global__ void att_scatter_k(const float* __restrict__ w, const float* __restrict__ den,
                              const float* __restrict__ edge,
                              const int* __restrict__ es_all, const int* __restrict__ ed_all,
                              float* __restrict__ gatt)
{
    int idx = blockIdx.x * blockDim.x + threadIdx.x;
    if (idx >= B_ * EA_ * (D_ / 4)) return;
    int eg = idx >> 7;
    int j  = (idx & 127) << 2;
    int b  = eg >> 16;
    int e  = eg & (EA_ - 1);
    int s = __ldg(es_all + (size_t)b * EA_ + e);
    int d = __ldg(ed_all + (size_t)b * EA_ + e);
    float dn = __ldg(den + b * N_ + d);
    float sc = __ldg(w + eg) / (dn > 0.f ? dn : 1.f);
    float4 v = *reinterpret_cast<const float4*>(edge + ((size_t)b * M_ + s) * D_ + j);
    red_add_v4(gatt + ((size_t)b * N_ + d) * D_ + j, sc * v.x, sc * v.y, sc * v.z, sc * v.w);
}

__global__ void new1_k(const float* __restrict__ tok, const float* __restrict__ gatt,
                       const float* __restrict__ ga, float* __restrict__ out)
{
    int idx = blockIdx.x * blockDim.x + threadIdx.x;
    if (idx >= (int)((size_t)BN_ALL * D_ / 4)) return;
    float g = tanhf(ga[0]);
    float4 t = reinterpret_cast<const float4*>(tok)[idx];
    float4 a = reinterpret_cast<const float4*>(gatt)[idx];
    float4 o;
    o.x = t.x + g * a.x; o.y = t.y + g * a.y; o.z = t.z + g * a.z; o.w = t.w + g * a.w;
    reinterpret_cast<float4*>(out)[idx] = o;
}

// out = resid + tanh(gate) * (x + bias)
__global__ void epi_k(const float* __restrict__ x, const float* __restrict__ bias,
                      const float* __restrict__ resid, const float* __restrict__ gate,
                      float* __restrict__ out)
{
    int idx = blockIdx.x * blockDim.x + threadIdx.x;
    if (idx >= (int)((size_t)BN_ALL * D_ / 4)) return;
    int c = (idx & 127) << 2;
    float g = tanhf(gate[0]);
    float4 v = reinterpret_cast<const float4*>(x)[idx];
    float4 b = *reinterpret_cast<const float4*>(bias + c);
    float4 r = reinterpret_cast<const float4*>(resid)[idx];
    float4 o;
    o.x = r.x + g * (v.x + b.x); o.y = r.y + g * (v.y + b.y);
    o.z = r.z + g * (v.z + b.z); o.w = r.w + g * (v.w + b.w);
    reinterpret_cast<float4*>(out)[idx] = o;
}

// ---------------- launch ----------------------------------------------------------
extern "C" void kernel_launch(void* const* d_in, const int* in_sizes, int n_in,
                              void* d_out, int out_size)
{
    (void)in_sizes; (void)n_in; (void)out_size;

    const float* tok = (const float*)d_in[0];
    const int*   t2e = (const int*)d_in[1];
    const int*   ei  = (const int*)d_in[2];
    const int*   aes = (const int*)d_in[3];
    const int*   aed = (const int*)d_in[4];
    const float* Wg = (const float*)d_in[5];
    const float* bg = (const float*)d_in[6];
    const float* Wk = (const float*)d_in[7];
    const float* bk = (const float*)d_in[8];
    const float* Wq = (const float*)d_in[9];
    const float* bq = (const float*)d_in[10];
    const float* Wl = (const float*)d_in[11];
    const float* bl = (const float*)d_in[12];
    const float* ga = (const float*)d_in[13];
    const float* gb = (const float*)d_in[14];
    float* out = (float*)d_out;

    float* base = nullptr;
    cudaGetSymbolAddress((void**)&base, g_scratch);

    float*    tw    = base + OFF_TW;
    float*    edge  = base + OFF_EDGE;
    float*    kbuf  = base + OFF_K;
    float*    qbuf  = base + OFF_Q;
    float*    new1  = base + OFF_NEW1;
    float*    gatt  = base + OFF_GATT;
    float*    deg   = base + OFF_DEG;
    unsigned* menc  = (unsigned*)(base + OFF_MENC);
    float*    den   = base + OFF_DEN;
    float*    dots  = base + OFF_DOTS;
    float*    wbuf  = base + OFF_W;
    uint4*    tokp  = (uint4*)(base + OFF_TOKP);
    uint4*    edgep = (uint4*)(base + OFF_EDGEP);
    uint4*    n1p   = (uint4*)(base + OFF_N1P);
    uint4*    wgp   = (uint4*)(base + OFF_WGP);
    uint4*    wlp   = (uint4*)(base + OFF_WLP);
    uint4*    wkp   = (uint4*)(base + OFF_WKP);
    uint4*    wqp   = (uint4*)(base + OFF_WQP);

    const int T = 256;

    // weight packing (fragment-major, hi/lo split)
    wpack_k<<<((D_ / 8) * 1024 + T - 1) / T, T>>>(Wg, D_, wgp);
    wpack_k<<<((D_ / 8) * 1024 + T - 1) / T, T>>>(Wl, D_, wlp);
    wpack_k<<<((DK_ / 8) * 1024 + T - 1) / T, T>>>(Wk, DK_, wkp);
    wpack_k<<<((DK_ / 8) * 1024 + T - 1) / T, T>>>(Wq, DK_, wqp);

    init_k<<<(int)(((size_t)BN_ALL * D_ / 4 + T - 1) / T), T>>>(deg, menc, den, gatt);

    // pack tok, then tw = tok @ Wg ; q = tok @ Wq + bq  (tok pack shared)
    apack_k<<<((BN_ALL / 16) * 1024 + T - 1) / T, T>>>(tok, BN_ALL, tokp);
    gemm_mma_pk<<<dim3(BN_ALL / 128, D_ / 64), 256>>>(BN_ALL, D_, tokp, wgp, nullptr, tw);
    gemm_mma_pk<<<dim3(BN_ALL / 128, 1), 256>>>(BN_ALL, DK_, tokp, wqp, bq, qbuf);

    deg_add_k<<<(B_ * EG_ + T - 1) / T, T>>>(ei, deg);
    gcn_self_k<<<(BM_ALL * (D_ / 4) + T - 1) / T, T>>>(tw, deg, t2e, bg, edge);
    gcn_scatter_k<<<(int)(((size_t)B_ * EG_ * (D_ / 4) + T - 1) / T), T>>>(tw, deg, t2e, ei, edge);

    // pack edge, then k = edge @ Wk + bk
    apack_k<<<((BM_ALL / 16) * 1024 + T - 1) / T, T>>>(edge, BM_ALL, edgep);
    gemm_mma_pk<<<dim3(BM_ALL / 128, 1), 256>>>(BM_ALL, DK_, edgep, wkp, bk, kbuf);

    att_dot_k<<<(int)(((size_t)B_ * EA_ * 32 + T - 1) / T), T>>>(qbuf, kbuf, aes, aed, dots, menc);
    att_w_k<<<(B_ * EA_ + T - 1) / T, T>>>(dots, menc, aed, wbuf, den);
    att_scatter_k<<<(int)(((size_t)B_ * EA_ * (D_ / 4) + T - 1) / T), T>>>(wbuf, den, edge, aes, aed, gatt);

    new1_k<<<(int)(((size_t)BN_ALL * D_ / 4 + T - 1) / T), T>>>(tok, gatt, ga, new1);

    // pack new1; raw = new1 @ Wl (into dead tw buffer); out = new1 + tanh(gb)*(raw + bl)
    apack_k<<<((BN_ALL / 16) * 1024 + T - 1) / T, T>>>(new1, BN_ALL, n1p);
    gemm_mma_pk<<<dim3(BN_ALL / 128, D_ / 64), 256>>>(BN_ALL, D_, n1p, wlp, nullptr, tw);
    epi_k<<<(int)(((size_t)BN_ALL * D_ / 4 + T - 1) / T), T>>>(tw, bl, new1, gb, out);
}